// round 1
// baseline (speedup 1.0000x reference)
#include <cuda_runtime.h>
#include <math.h>

#define TOK 2048
#define HD  1024
#define ID  2048
#define NE  8

// ---------------- scratch (device globals: no allocation allowed) ----------
__device__ float g_xs[(size_t)TOK * HD];        // score-scaled tokens (routed input)
__device__ float g_act[(size_t)TOK * ID];       // SwiGLU activations (reused shared->routed)
__device__ int   g_expert[TOK];
__device__ int   g_counts[NE];
__device__ int   g_offsets[NE];
__device__ int   g_cursor[NE];
__device__ int   g_sorted[TOK];

// ---------------- small kernels --------------------------------------------
__global__ void init_kernel() {
    if (threadIdx.x < NE) g_counts[threadIdx.x] = 0;
}

__global__ void router_kernel(const float* __restrict__ x,
                              const float* __restrict__ gate_w) {
    int warp = (blockIdx.x * blockDim.x + threadIdx.x) >> 5;
    int lane = threadIdx.x & 31;
    if (warp >= TOK) return;
    const float* xr = x + (size_t)warp * HD;
    float acc[NE];
#pragma unroll
    for (int e = 0; e < NE; e++) acc[e] = 0.f;
    for (int h = lane; h < HD; h += 32) {
        float xv = xr[h];
        const float* w = gate_w + (size_t)h * NE;
#pragma unroll
        for (int e = 0; e < NE; e++) acc[e] = fmaf(xv, w[e], acc[e]);
    }
#pragma unroll
    for (int e = 0; e < NE; e++) {
#pragma unroll
        for (int o = 16; o > 0; o >>= 1)
            acc[e] += __shfl_xor_sync(0xffffffffu, acc[e], o);
    }
    int best = 0; float bv = acc[0];
#pragma unroll
    for (int e = 1; e < NE; e++) if (acc[e] > bv) { bv = acc[e]; best = e; }
    float score = 1.f / (1.f + expf(-bv));
    if (lane == 0) {
        g_expert[warp] = best;
        atomicAdd(&g_counts[best], 1);
    }
    float* dst = g_xs + (size_t)warp * HD;
    for (int h = lane; h < HD; h += 32) dst[h] = xr[h] * score;
}

__global__ void scan_kernel() {
    if (threadIdx.x == 0) {
        int off = 0;
        for (int e = 0; e < NE; e++) {
            g_offsets[e] = off;
            g_cursor[e]  = off;
            off += g_counts[e];
        }
    }
}

__global__ void build_sorted_kernel() {
    int t = blockIdx.x * blockDim.x + threadIdx.x;
    if (t >= TOK) return;
    int e = g_expert[t];
    int pos = atomicAdd(&g_cursor[e], 1);
    g_sorted[pos] = t;
}

// ---------------- GEMM stage 1: act = silu(A@Wg) * (A@Wu) ------------------
// Tile 64x64, BK=16, 256 threads, 4x4 per thread, dual accumulator (gate+up).
template <bool ROUTED>
__global__ void __launch_bounds__(256)
gemm1_kernel(const float* __restrict__ Ain,
             const float* __restrict__ Wg_base,
             const float* __restrict__ Wu_base) {
    const int e       = ROUTED ? blockIdx.z : 0;
    const int rows    = ROUTED ? g_counts[e] : TOK;
    const int row_off = ROUTED ? g_offsets[e] : 0;
    const int mtile   = blockIdx.y;
    if (mtile * 64 >= rows) return;
    const int ntile = blockIdx.x;

    const float* A = ROUTED ? g_xs : Ain;
    const size_t wofs = ROUTED ? (size_t)e * HD * ID : 0;
    const float* Wg = Wg_base + wofs;
    const float* Wu = Wu_base + wofs;

    __shared__ __align__(16) float As[16][64];
    __shared__ __align__(16) float Bg[16][64];
    __shared__ __align__(16) float Bu[16][64];

    const int tid = threadIdx.x;
    const int tx = tid & 15;
    const int ty = tid >> 4;

    // A load: row = tid/4 (0..63), k-quad = (tid%4)*4
    const int ar   = tid >> 2;
    const int akq  = (tid & 3) << 2;
    const int arow = mtile * 64 + ar;
    int a_src = -1;
    if (arow < rows) a_src = ROUTED ? g_sorted[row_off + arow] : arow;

    // B load: k = tid/16 (0..15), n-quad = (tid%16)*4
    const int bkr   = tid >> 4;
    const int bnq   = (tid & 15) << 2;
    const int ncol0 = ntile * 64;

    float accg[4][4] = {};
    float accu[4][4] = {};

    for (int kb = 0; kb < HD; kb += 16) {
        float4 av = make_float4(0.f, 0.f, 0.f, 0.f);
        if (a_src >= 0)
            av = *(const float4*)(A + (size_t)a_src * HD + kb + akq);
        As[akq + 0][ar] = av.x;
        As[akq + 1][ar] = av.y;
        As[akq + 2][ar] = av.z;
        As[akq + 3][ar] = av.w;
        *(float4*)&Bg[bkr][bnq] =
            *(const float4*)(Wg + (size_t)(kb + bkr) * ID + ncol0 + bnq);
        *(float4*)&Bu[bkr][bnq] =
            *(const float4*)(Wu + (size_t)(kb + bkr) * ID + ncol0 + bnq);
        __syncthreads();
#pragma unroll
        for (int kk = 0; kk < 16; kk++) {
            float4 a4  = *(const float4*)&As[kk][ty << 2];
            float4 g4  = *(const float4*)&Bg[kk][tx << 2];
            float4 u4  = *(const float4*)&Bu[kk][tx << 2];
            float a[4]  = {a4.x, a4.y, a4.z, a4.w};
            float bg[4] = {g4.x, g4.y, g4.z, g4.w};
            float bu[4] = {u4.x, u4.y, u4.z, u4.w};
#pragma unroll
            for (int i = 0; i < 4; i++)
#pragma unroll
                for (int j = 0; j < 4; j++) {
                    accg[i][j] = fmaf(a[i], bg[j], accg[i][j]);
                    accu[i][j] = fmaf(a[i], bu[j], accu[i][j]);
                }
        }
        __syncthreads();
    }

#pragma unroll
    for (int i = 0; i < 4; i++) {
        int r = mtile * 64 + (ty << 2) + i;
        if (r >= rows) break;
        int orow = ROUTED ? (row_off + r) : r;   // routed act stored in sorted order
        float* dst = g_act + (size_t)orow * ID + ncol0 + (tx << 2);
#pragma unroll
        for (int j = 0; j < 4; j++) {
            float g = accg[i][j];
            float s = g / (1.f + expf(-g));      // silu(g)
            dst[j]  = s * accu[i][j];
        }
    }
}

// ---------------- GEMM stage 2: out (+)= act @ Wd ---------------------------
template <bool ROUTED>
__global__ void __launch_bounds__(256)
gemm2_kernel(const float* __restrict__ Wd_base, float* __restrict__ out) {
    const int e       = ROUTED ? blockIdx.z : 0;
    const int rows    = ROUTED ? g_counts[e] : TOK;
    const int row_off = ROUTED ? g_offsets[e] : 0;
    const int mtile   = blockIdx.y;
    if (mtile * 64 >= rows) return;
    const int ntile = blockIdx.x;
    const float* Wd = Wd_base + (ROUTED ? (size_t)e * ID * HD : 0);

    __shared__ __align__(16) float As[16][64];
    __shared__ __align__(16) float Bs[16][64];

    const int tid = threadIdx.x;
    const int tx = tid & 15;
    const int ty = tid >> 4;

    const int ar   = tid >> 2;
    const int akq  = (tid & 3) << 2;
    const int arow = mtile * 64 + ar;
    const bool avalid = arow < rows;
    const size_t a_row = (size_t)(row_off + arow);  // sorted storage (identity if shared)

    const int bkr   = tid >> 4;
    const int bnq   = (tid & 15) << 2;
    const int ncol0 = ntile * 64;

    float acc[4][4] = {};

    for (int kb = 0; kb < ID; kb += 16) {
        float4 av = make_float4(0.f, 0.f, 0.f, 0.f);
        if (avalid)
            av = *(const float4*)(g_act + a_row * ID + kb + akq);
        As[akq + 0][ar] = av.x;
        As[akq + 1][ar] = av.y;
        As[akq + 2][ar] = av.z;
        As[akq + 3][ar] = av.w;
        *(float4*)&Bs[bkr][bnq] =
            *(const float4*)(Wd + (size_t)(kb + bkr) * HD + ncol0 + bnq);
        __syncthreads();
#pragma unroll
        for (int kk = 0; kk < 16; kk++) {
            float4 a4 = *(const float4*)&As[kk][ty << 2];
            float4 b4 = *(const float4*)&Bs[kk][tx << 2];
            float a[4] = {a4.x, a4.y, a4.z, a4.w};
            float b[4] = {b4.x, b4.y, b4.z, b4.w};
#pragma unroll
            for (int i = 0; i < 4; i++)
#pragma unroll
                for (int j = 0; j < 4; j++)
                    acc[i][j] = fmaf(a[i], b[j], acc[i][j]);
        }
        __syncthreads();
    }

#pragma unroll
    for (int i = 0; i < 4; i++) {
        int r = mtile * 64 + (ty << 2) + i;
        if (r >= rows) break;
        int token = ROUTED ? g_sorted[row_off + r] : r;
        float* dst = out + (size_t)token * HD + ncol0 + (tx << 2);
        if (ROUTED) {
#pragma unroll
            for (int j = 0; j < 4; j++) dst[j] += acc[i][j];  // unique per token: race-free
        } else {
#pragma unroll
            for (int j = 0; j < 4; j++) dst[j] = acc[i][j];   // initializes full output
        }
    }
}

// ---------------- launch -----------------------------------------------------
extern "C" void kernel_launch(void* const* d_in, const int* in_sizes, int n_in,
                              void* d_out, int out_size) {
    (void)in_sizes; (void)n_in; (void)out_size;
    const float* x       = (const float*)d_in[0];
    const float* gate_w  = (const float*)d_in[1];
    const float* sh_gate = (const float*)d_in[2];
    const float* sh_up   = (const float*)d_in[3];
    const float* sh_down = (const float*)d_in[4];
    const float* rt_gate = (const float*)d_in[5];
    const float* rt_up   = (const float*)d_in[6];
    const float* rt_down = (const float*)d_in[7];
    float* out = (float*)d_out;

    init_kernel<<<1, 32>>>();
    router_kernel<<<TOK / 8, 256>>>(x, gate_w);
    scan_kernel<<<1, 32>>>();
    build_sorted_kernel<<<TOK / 256, 256>>>();

    // shared expert: writes full output (covers 0xAA poison)
    gemm1_kernel<false><<<dim3(ID / 64, TOK / 64, 1), 256>>>(x, sh_gate, sh_up);
    gemm2_kernel<false><<<dim3(HD / 64, TOK / 64, 1), 256>>>(sh_down, out);

    // routed experts: grouped GEMM over sorted token lists, scatter-add
    gemm1_kernel<true><<<dim3(ID / 64, TOK / 64, NE), 256>>>(nullptr, rt_gate, rt_up);
    gemm2_kernel<true><<<dim3(HD / 64, TOK / 64, NE), 256>>>(rt_down, out);
}

// round 6
// speedup vs baseline: 2.3474x; 2.3474x over previous
#include <cuda_runtime.h>
#include <cuda_bf16.h>
#include <math.h>
#include <stdint.h>

#define TOK 2048
#define HD  1024
#define ID  2048
#define NE  8
#define PAD 128
#define RS  40   // smem row stride in bf16 elements (80B) -> conflict-free frags

// ---------------- scratch (device globals; small, like passing R1) ----------
__device__ __align__(256) float g_xs[(size_t)TOK * HD];          // score-scaled tokens
__device__ __align__(256) float g_act[(size_t)(TOK + PAD) * ID]; // activations fp32
__device__ int g_expert[TOK];
__device__ int g_counts[NE];
__device__ int g_offsets[NE];
__device__ int g_cursor[NE];
__device__ int g_sorted[TOK];

// ---------------- helpers ----------------------------------------------------
__device__ __forceinline__ void mma16816(float* d, const uint32_t* a, const uint32_t* b) {
    asm volatile(
        "mma.sync.aligned.m16n8k16.row.col.f32.bf16.bf16.f32 "
        "{%0,%1,%2,%3}, {%4,%5,%6,%7}, {%8,%9}, {%0,%1,%2,%3};"
        : "+f"(d[0]), "+f"(d[1]), "+f"(d[2]), "+f"(d[3])
        : "r"(a[0]), "r"(a[1]), "r"(a[2]), "r"(a[3]), "r"(b[0]), "r"(b[1]));
}
__device__ __forceinline__ uint32_t packbf(__nv_bfloat16 a, __nv_bfloat16 b) {
    __nv_bfloat162 t; t.x = a; t.y = b;
    return reinterpret_cast<uint32_t&>(t);
}

// ---------------- small kernels (identical to passing R1) --------------------
__global__ void init_kernel() {
    if (threadIdx.x < NE) g_counts[threadIdx.x] = 0;
}

__global__ void router_kernel(const float* __restrict__ x,
                              const float* __restrict__ gate_w) {
    int warp = (blockIdx.x * blockDim.x + threadIdx.x) >> 5;
    int lane = threadIdx.x & 31;
    if (warp >= TOK) return;
    const float* xr = x + (size_t)warp * HD;
    float acc[NE];
#pragma unroll
    for (int e = 0; e < NE; e++) acc[e] = 0.f;
    for (int h = lane; h < HD; h += 32) {
        float xv = xr[h];
        const float* w = gate_w + (size_t)h * NE;
#pragma unroll
        for (int e = 0; e < NE; e++) acc[e] = fmaf(xv, w[e], acc[e]);
    }
#pragma unroll
    for (int e = 0; e < NE; e++) {
#pragma unroll
        for (int o = 16; o > 0; o >>= 1)
            acc[e] += __shfl_xor_sync(0xffffffffu, acc[e], o);
    }
    int best = 0; float bv = acc[0];
#pragma unroll
    for (int e = 1; e < NE; e++) if (acc[e] > bv) { bv = acc[e]; best = e; }
    float score = 1.f / (1.f + expf(-bv));
    if (lane == 0) {
        g_expert[warp] = best;
        atomicAdd(&g_counts[best], 1);
    }
    float* dst = g_xs + (size_t)warp * HD;
    for (int h = lane; h < HD; h += 32) dst[h] = xr[h] * score;
}

__global__ void scan_kernel() {
    if (threadIdx.x == 0) {
        int off = 0;
        for (int e = 0; e < NE; e++) {
            g_offsets[e] = off;
            g_cursor[e]  = off;
            off += g_counts[e];
        }
    }
}

__global__ void build_sorted_kernel() {
    int t = blockIdx.x * blockDim.x + threadIdx.x;
    if (t >= TOK) return;
    int e = g_expert[t];
    int pos = atomicAdd(&g_cursor[e], 1);
    g_sorted[pos] = t;
}

// ---------------- GEMM1: act = silu(A@Wg)*(A@Wu) -----------------------------
// Tile M=128 x N=64, K-chunk 32. fp32 global loads, in-kernel bf16 hi/lo split.
// A [m][k] natural; B (weights [k][n]) transposed into smem [n][k].
template <bool ROUTED>
__global__ void __launch_bounds__(256) gemm1_mma(const float* __restrict__ xin,
                                                 const float* __restrict__ Wg_all,
                                                 const float* __restrict__ Wu_all) {
    const int e       = ROUTED ? blockIdx.z : 0;
    const int rows    = ROUTED ? g_counts[e] : TOK;
    const int row_off = ROUTED ? g_offsets[e] : 0;
    const int mtile   = blockIdx.y;
    if (mtile * 128 >= rows) return;
    const int ncol0 = blockIdx.x * 64;

    __shared__ __align__(16) __nv_bfloat16 sAh[128 * RS];
    __shared__ __align__(16) __nv_bfloat16 sAl[128 * RS];
    __shared__ __align__(16) __nv_bfloat16 sGh[64 * RS];
    __shared__ __align__(16) __nv_bfloat16 sGl[64 * RS];
    __shared__ __align__(16) __nv_bfloat16 sUh[64 * RS];
    __shared__ __align__(16) __nv_bfloat16 sUl[64 * RS];

    const int tid = threadIdx.x, wid = tid >> 5, lane = tid & 31;
    const int wm = wid >> 1, wn = wid & 1;

    // A loader: thread covers row ar (0..127), 16 fp32 cols at acq
    const int ar  = tid >> 1;
    const int acq = (tid & 1) * 16;
    const float* Arow;
    if (ROUTED) {
        int sr = row_off + mtile * 128 + ar;
        sr = sr < TOK ? sr : TOK - 1;           // clamp (masked in epilogue)
        Arow = g_xs + (size_t)g_sorted[sr] * HD;
    } else {
        Arow = xin + (size_t)(mtile * 128 + ar) * HD;
    }
    // B loader: lane-along-k. k = bk (0..31), n block of 8 at bn.
    const int bk = tid & 31;
    const int bn = (tid >> 5) * 8;
    const float* Wg = Wg_all + (ROUTED ? (size_t)e * HD * ID : 0);
    const float* Wu = Wu_all + (ROUTED ? (size_t)e * HD * ID : 0);

    float4 va[4], vg[2], vu[2];
#define G1_LOAD(kb)                                                            \
    do {                                                                       \
        _Pragma("unroll")                                                      \
        for (int q = 0; q < 4; q++)                                            \
            va[q] = *(const float4*)(Arow + (kb) + acq + q * 4);               \
        const float* wgp = Wg + (size_t)((kb) + bk) * ID + ncol0 + bn;         \
        const float* wup = Wu + (size_t)((kb) + bk) * ID + ncol0 + bn;         \
        vg[0] = *(const float4*)(wgp);     vg[1] = *(const float4*)(wgp + 4);  \
        vu[0] = *(const float4*)(wup);     vu[1] = *(const float4*)(wup + 4);  \
    } while (0)

    float accg[2][4][4] = {};
    float accu[2][4][4] = {};

    const int NCH = HD / 32;
    G1_LOAD(0);
    for (int ch = 0; ch < NCH; ch++) {
        __syncthreads();
        // ---- store current chunk to smem (split hi/lo, transpose B) ----
#pragma unroll
        for (int q = 0; q < 4; q++) {
            float4 v = va[q];
            __nv_bfloat16 hx = __float2bfloat16(v.x), hy = __float2bfloat16(v.y);
            __nv_bfloat16 hz = __float2bfloat16(v.z), hw = __float2bfloat16(v.w);
            __nv_bfloat16 lx = __float2bfloat16(v.x - __bfloat162float(hx));
            __nv_bfloat16 ly = __float2bfloat16(v.y - __bfloat162float(hy));
            __nv_bfloat16 lz = __float2bfloat16(v.z - __bfloat162float(hz));
            __nv_bfloat16 lw = __float2bfloat16(v.w - __bfloat162float(hw));
            int c = acq + q * 4;
            *(uint32_t*)&sAh[ar * RS + c]     = packbf(hx, hy);
            *(uint32_t*)&sAh[ar * RS + c + 2] = packbf(hz, hw);
            *(uint32_t*)&sAl[ar * RS + c]     = packbf(lx, ly);
            *(uint32_t*)&sAl[ar * RS + c + 2] = packbf(lz, lw);
        }
#pragma unroll
        for (int m = 0; m < 2; m++) {
            float gv[4] = {vg[m].x, vg[m].y, vg[m].z, vg[m].w};
            float uv[4] = {vu[m].x, vu[m].y, vu[m].z, vu[m].w};
#pragma unroll
            for (int j = 0; j < 4; j++) {
                int n = bn + m * 4 + j;
                __nv_bfloat16 h = __float2bfloat16(gv[j]);
                sGh[n * RS + bk] = h;
                sGl[n * RS + bk] = __float2bfloat16(gv[j] - __bfloat162float(h));
                __nv_bfloat16 h2 = __float2bfloat16(uv[j]);
                sUh[n * RS + bk] = h2;
                sUl[n * RS + bk] = __float2bfloat16(uv[j] - __bfloat162float(h2));
            }
        }
        __syncthreads();
        if (ch + 1 < NCH) G1_LOAD((ch + 1) * 32);   // overlaps MMAs below

        // ---- MMAs ----
#pragma unroll
        for (int hf = 0; hf < 2; hf++) {
            const int k0 = hf * 16;
            uint32_t afh[2][4], afl[2][4];
#pragma unroll
            for (int am = 0; am < 2; am++) {
                int r = wm * 32 + am * 16 + (lane >> 2);
                int c = k0 + (lane & 3) * 2;
                afh[am][0] = *(const uint32_t*)&sAh[r * RS + c];
                afh[am][1] = *(const uint32_t*)&sAh[(r + 8) * RS + c];
                afh[am][2] = *(const uint32_t*)&sAh[r * RS + c + 8];
                afh[am][3] = *(const uint32_t*)&sAh[(r + 8) * RS + c + 8];
                afl[am][0] = *(const uint32_t*)&sAl[r * RS + c];
                afl[am][1] = *(const uint32_t*)&sAl[(r + 8) * RS + c];
                afl[am][2] = *(const uint32_t*)&sAl[r * RS + c + 8];
                afl[am][3] = *(const uint32_t*)&sAl[(r + 8) * RS + c + 8];
            }
#pragma unroll
            for (int an = 0; an < 4; an++) {
                int n = wn * 32 + an * 8 + (lane >> 2);
                int c = k0 + (lane & 3) * 2;
                uint32_t bh[2], bl[2], uh[2], ul[2];
                bh[0] = *(const uint32_t*)&sGh[n * RS + c];
                bh[1] = *(const uint32_t*)&sGh[n * RS + c + 8];
                bl[0] = *(const uint32_t*)&sGl[n * RS + c];
                bl[1] = *(const uint32_t*)&sGl[n * RS + c + 8];
                uh[0] = *(const uint32_t*)&sUh[n * RS + c];
                uh[1] = *(const uint32_t*)&sUh[n * RS + c + 8];
                ul[0] = *(const uint32_t*)&sUl[n * RS + c];
                ul[1] = *(const uint32_t*)&sUl[n * RS + c + 8];
#pragma unroll
                for (int am = 0; am < 2; am++) {
                    mma16816(accg[am][an], afh[am], bh);
                    mma16816(accg[am][an], afh[am], bl);
                    mma16816(accg[am][an], afl[am], bh);
                    mma16816(accu[am][an], afh[am], uh);
                    mma16816(accu[am][an], afh[am], ul);
                    mma16816(accu[am][an], afl[am], uh);
                }
            }
        }
    }
#undef G1_LOAD

    // epilogue: silu(g)*u -> fp32 g_act (sorted order for routed)
    const int obase = (ROUTED ? row_off : 0) + mtile * 128;
#pragma unroll
    for (int am = 0; am < 2; am++)
#pragma unroll
        for (int an = 0; an < 4; an++) {
            int rl0 = wm * 32 + am * 16 + (lane >> 2);
            int col = ncol0 + wn * 32 + an * 8 + (lane & 3) * 2;
#pragma unroll
            for (int h = 0; h < 2; h++) {
                int rl = rl0 + h * 8;
                if (mtile * 128 + rl < rows) {
                    float g0 = accg[am][an][h * 2], g1 = accg[am][an][h * 2 + 1];
                    float u0 = accu[am][an][h * 2], u1 = accu[am][an][h * 2 + 1];
                    float v0 = g0 / (1.f + __expf(-g0)) * u0;
                    float v1 = g1 / (1.f + __expf(-g1)) * u1;
                    *(float2*)(g_act + (size_t)(obase + rl) * ID + col) =
                        make_float2(v0, v1);
                }
            }
        }
}

// ---------------- GEMM2: out (+)= act @ Wd -----------------------------------
// Tile M=128 x N=128, K-chunk 32.
template <bool ROUTED>
__global__ void __launch_bounds__(256) gemm2_mma(const float* __restrict__ Wd_all,
                                                 float* __restrict__ out) {
    const int e       = ROUTED ? blockIdx.z : 0;
    const int rows    = ROUTED ? g_counts[e] : TOK;
    const int row_off = ROUTED ? g_offsets[e] : 0;
    const int mtile   = blockIdx.y;
    if (mtile * 128 >= rows) return;
    const int ncol0 = blockIdx.x * 128;

    __shared__ __align__(16) __nv_bfloat16 sAh[128 * RS];
    __shared__ __align__(16) __nv_bfloat16 sAl[128 * RS];
    __shared__ __align__(16) __nv_bfloat16 sWh[128 * RS];
    __shared__ __align__(16) __nv_bfloat16 sWl[128 * RS];

    const int tid = threadIdx.x, wid = tid >> 5, lane = tid & 31;
    const int wm = wid >> 1, wn = wid & 1;

    const int ar  = tid >> 1;
    const int acq = (tid & 1) * 16;
    const int abase = (ROUTED ? row_off : 0) + mtile * 128;
    const float* Arow = g_act + (size_t)(abase + ar) * ID;

    const int bk = tid & 31;
    const int bn = (tid >> 5) * 16;
    const float* Wd = Wd_all + (ROUTED ? (size_t)e * ID * HD : 0);

    float4 va[4], vw[4];
#define G2_LOAD(kb)                                                            \
    do {                                                                       \
        _Pragma("unroll")                                                      \
        for (int q = 0; q < 4; q++)                                            \
            va[q] = *(const float4*)(Arow + (kb) + acq + q * 4);               \
        const float* wdp = Wd + (size_t)((kb) + bk) * HD + ncol0 + bn;         \
        _Pragma("unroll")                                                      \
        for (int q = 0; q < 4; q++)                                            \
            vw[q] = *(const float4*)(wdp + q * 4);                             \
    } while (0)

    float acc[2][8][4] = {};

    const int NCH = ID / 32;
    G2_LOAD(0);
    for (int ch = 0; ch < NCH; ch++) {
        __syncthreads();
#pragma unroll
        for (int q = 0; q < 4; q++) {
            float4 v = va[q];
            __nv_bfloat16 hx = __float2bfloat16(v.x), hy = __float2bfloat16(v.y);
            __nv_bfloat16 hz = __float2bfloat16(v.z), hw = __float2bfloat16(v.w);
            __nv_bfloat16 lx = __float2bfloat16(v.x - __bfloat162float(hx));
            __nv_bfloat16 ly = __float2bfloat16(v.y - __bfloat162float(hy));
            __nv_bfloat16 lz = __float2bfloat16(v.z - __bfloat162float(hz));
            __nv_bfloat16 lw = __float2bfloat16(v.w - __bfloat162float(hw));
            int c = acq + q * 4;
            *(uint32_t*)&sAh[ar * RS + c]     = packbf(hx, hy);
            *(uint32_t*)&sAh[ar * RS + c + 2] = packbf(hz, hw);
            *(uint32_t*)&sAl[ar * RS + c]     = packbf(lx, ly);
            *(uint32_t*)&sAl[ar * RS + c + 2] = packbf(lz, lw);
        }
#pragma unroll
        for (int q = 0; q < 4; q++) {
            float wv[4] = {vw[q].x, vw[q].y, vw[q].z, vw[q].w};
#pragma unroll
            for (int j = 0; j < 4; j++) {
                int n = bn + q * 4 + j;
                __nv_bfloat16 h = __float2bfloat16(wv[j]);
                sWh[n * RS + bk] = h;
                sWl[n * RS + bk] = __float2bfloat16(wv[j] - __bfloat162float(h));
            }
        }
        __syncthreads();
        if (ch + 1 < NCH) G2_LOAD((ch + 1) * 32);

#pragma unroll
        for (int hf = 0; hf < 2; hf++) {
            const int k0 = hf * 16;
            uint32_t afh[2][4], afl[2][4];
#pragma unroll
            for (int am = 0; am < 2; am++) {
                int r = wm * 32 + am * 16 + (lane >> 2);
                int c = k0 + (lane & 3) * 2;
                afh[am][0] = *(const uint32_t*)&sAh[r * RS + c];
                afh[am][1] = *(const uint32_t*)&sAh[(r + 8) * RS + c];
                afh[am][2] = *(const uint32_t*)&sAh[r * RS + c + 8];
                afh[am][3] = *(const uint32_t*)&sAh[(r + 8) * RS + c + 8];
                afl[am][0] = *(const uint32_t*)&sAl[r * RS + c];
                afl[am][1] = *(const uint32_t*)&sAl[(r + 8) * RS + c];
                afl[am][2] = *(const uint32_t*)&sAl[r * RS + c + 8];
                afl[am][3] = *(const uint32_t*)&sAl[(r + 8) * RS + c + 8];
            }
#pragma unroll
            for (int an = 0; an < 8; an++) {
                int n = wn * 64 + an * 8 + (lane >> 2);
                int c = k0 + (lane & 3) * 2;
                uint32_t bh[2], bl[2];
                bh[0] = *(const uint32_t*)&sWh[n * RS + c];
                bh[1] = *(const uint32_t*)&sWh[n * RS + c + 8];
                bl[0] = *(const uint32_t*)&sWl[n * RS + c];
                bl[1] = *(const uint32_t*)&sWl[n * RS + c + 8];
#pragma unroll
                for (int am = 0; am < 2; am++) {
                    mma16816(acc[am][an], afh[am], bh);
                    mma16816(acc[am][an], afh[am], bl);
                    mma16816(acc[am][an], afl[am], bh);
                }
            }
        }
    }
#undef G2_LOAD

    // epilogue: write/accumulate fp32 output per token
#pragma unroll
    for (int am = 0; am < 2; am++)
#pragma unroll
        for (int an = 0; an < 8; an++) {
            int rl0 = wm * 32 + am * 16 + (lane >> 2);
            int col = ncol0 + wn * 64 + an * 8 + (lane & 3) * 2;
#pragma unroll
            for (int h = 0; h < 2; h++) {
                int rl = rl0 + h * 8;
                int r = mtile * 128 + rl;
                if (r < rows) {
                    int token = ROUTED ? g_sorted[row_off + r] : r;
                    float* po = out + (size_t)token * HD + col;
                    float v0 = acc[am][an][h * 2], v1 = acc[am][an][h * 2 + 1];
                    if (ROUTED) {
                        float2 o2 = *(float2*)po;
                        v0 += o2.x; v1 += o2.y;
                    }
                    *(float2*)po = make_float2(v0, v1);
                }
            }
        }
}

// ---------------- launch -----------------------------------------------------
extern "C" void kernel_launch(void* const* d_in, const int* in_sizes, int n_in,
                              void* d_out, int out_size) {
    (void)in_sizes; (void)n_in; (void)out_size;
    const float* x       = (const float*)d_in[0];
    const float* gate_w  = (const float*)d_in[1];
    const float* sh_gate = (const float*)d_in[2];
    const float* sh_up   = (const float*)d_in[3];
    const float* sh_down = (const float*)d_in[4];
    const float* rt_gate = (const float*)d_in[5];
    const float* rt_up   = (const float*)d_in[6];
    const float* rt_down = (const float*)d_in[7];
    float* out = (float*)d_out;

    // routing
    init_kernel<<<1, 32>>>();
    router_kernel<<<TOK / 8, 256>>>(x, gate_w);
    scan_kernel<<<1, 32>>>();
    build_sorted_kernel<<<TOK / 256, 256>>>();

    // shared expert first (act buffer reuse; writes full out, covers poison)
    gemm1_mma<false><<<dim3(ID / 64, TOK / 128, 1), 256>>>(x, sh_gate, sh_up);
    gemm2_mma<false><<<dim3(HD / 128, TOK / 128, 1), 256>>>(sh_down, out);

    // routed experts (scatter-add into out)
    gemm1_mma<true><<<dim3(ID / 64, TOK / 128, NE), 256>>>(x, rt_gate, rt_up);
    gemm2_mma<true><<<dim3(HD / 128, TOK / 128, NE), 256>>>(rt_down, out);
}

// round 7
// speedup vs baseline: 2.4177x; 1.0299x over previous
#include <cuda_runtime.h>
#include <cuda_bf16.h>
#include <math.h>
#include <stdint.h>

#define TOK 2048
#define HD  1024
#define ID  2048
#define NE  8
#define PAD 128
#define RS  24   // smem row stride in bf16 elems (48B): conflict-free fragments

// ---------------- scratch (device globals; keep SMALL — proven safe) --------
__device__ __align__(256) float g_xs[(size_t)TOK * HD];          // score-scaled tokens
__device__ __align__(256) float g_act[(size_t)(TOK + PAD) * ID]; // activations fp32
__device__ int g_expert[TOK];
__device__ int g_counts[NE];
__device__ int g_offsets[NE];
__device__ int g_cursor[NE];
__device__ int g_sorted[TOK];

// ---------------- helpers ----------------------------------------------------
__device__ __forceinline__ void mma16816(float* d, const uint32_t* a, const uint32_t* b) {
    asm volatile(
        "mma.sync.aligned.m16n8k16.row.col.f32.bf16.bf16.f32 "
        "{%0,%1,%2,%3}, {%4,%5,%6,%7}, {%8,%9}, {%0,%1,%2,%3};"
        : "+f"(d[0]), "+f"(d[1]), "+f"(d[2]), "+f"(d[3])
        : "r"(a[0]), "r"(a[1]), "r"(a[2]), "r"(a[3]), "r"(b[0]), "r"(b[1]));
}
__device__ __forceinline__ uint32_t packbf(__nv_bfloat16 a, __nv_bfloat16 b) {
    __nv_bfloat162 t; t.x = a; t.y = b;
    return reinterpret_cast<uint32_t&>(t);
}

// ---------------- small kernels (identical to passing R1/R6) -----------------
__global__ void init_kernel() {
    if (threadIdx.x < NE) g_counts[threadIdx.x] = 0;
}

__global__ void router_kernel(const float* __restrict__ x,
                              const float* __restrict__ gate_w) {
    int warp = (blockIdx.x * blockDim.x + threadIdx.x) >> 5;
    int lane = threadIdx.x & 31;
    if (warp >= TOK) return;
    const float* xr = x + (size_t)warp * HD;
    float acc[NE];
#pragma unroll
    for (int e = 0; e < NE; e++) acc[e] = 0.f;
    for (int h = lane; h < HD; h += 32) {
        float xv = xr[h];
        const float* w = gate_w + (size_t)h * NE;
#pragma unroll
        for (int e = 0; e < NE; e++) acc[e] = fmaf(xv, w[e], acc[e]);
    }
#pragma unroll
    for (int e = 0; e < NE; e++) {
#pragma unroll
        for (int o = 16; o > 0; o >>= 1)
            acc[e] += __shfl_xor_sync(0xffffffffu, acc[e], o);
    }
    int best = 0; float bv = acc[0];
#pragma unroll
    for (int e = 1; e < NE; e++) if (acc[e] > bv) { bv = acc[e]; best = e; }
    float score = 1.f / (1.f + expf(-bv));
    if (lane == 0) {
        g_expert[warp] = best;
        atomicAdd(&g_counts[best], 1);
    }
    float* dst = g_xs + (size_t)warp * HD;
    for (int h = lane; h < HD; h += 32) dst[h] = xr[h] * score;
}

__global__ void scan_kernel() {
    if (threadIdx.x == 0) {
        int off = 0;
        for (int e = 0; e < NE; e++) {
            g_offsets[e] = off;
            g_cursor[e]  = off;
            off += g_counts[e];
        }
    }
}

__global__ void build_sorted_kernel() {
    int t = blockIdx.x * blockDim.x + threadIdx.x;
    if (t >= TOK) return;
    int e = g_expert[t];
    int pos = atomicAdd(&g_cursor[e], 1);
    g_sorted[pos] = t;
}

// ---------------- GEMM1: act = silu(A@Wg)*(A@Wu) -----------------------------
// Tile M=128 x N=64, K-chunk 16, double-buffered (2 x 24KB = 48KB static smem).
template <bool ROUTED>
__global__ void __launch_bounds__(256) gemm1_mma(const float* __restrict__ xin,
                                                 const float* __restrict__ Wg_all,
                                                 const float* __restrict__ Wu_all) {
    const int e       = ROUTED ? blockIdx.z : 0;
    const int rows    = ROUTED ? g_counts[e] : TOK;
    const int row_off = ROUTED ? g_offsets[e] : 0;
    const int mtile   = blockIdx.y;
    if (mtile * 128 >= rows) return;
    const int ncol0 = blockIdx.x * 64;

    __shared__ __align__(16) __nv_bfloat16 sAh[2][128 * RS];
    __shared__ __align__(16) __nv_bfloat16 sAl[2][128 * RS];
    __shared__ __align__(16) __nv_bfloat16 sGh[2][64 * RS];
    __shared__ __align__(16) __nv_bfloat16 sGl[2][64 * RS];
    __shared__ __align__(16) __nv_bfloat16 sUh[2][64 * RS];
    __shared__ __align__(16) __nv_bfloat16 sUl[2][64 * RS];

    const int tid = threadIdx.x, wid = tid >> 5, lane = tid & 31;
    const int wm = wid >> 1, wn = wid & 1;

    // A loader: row ar (0..127), 8 fp32 cols at acq
    const int ar  = tid >> 1;
    const int acq = (tid & 1) * 8;
    const float* Arow;
    if (ROUTED) {
        int sr = row_off + mtile * 128 + ar;
        sr = sr < TOK ? sr : TOK - 1;           // clamp (masked in epilogue)
        Arow = g_xs + (size_t)g_sorted[sr] * HD;
    } else {
        Arow = xin + (size_t)(mtile * 128 + ar) * HD;
    }
    // B loader: k = bk (0..15), 4 n at bn
    const int bk = tid & 15;
    const int bn = (tid >> 4) * 4;
    const float* Wg = Wg_all + (ROUTED ? (size_t)e * HD * ID : 0);
    const float* Wu = Wu_all + (ROUTED ? (size_t)e * HD * ID : 0);

    float4 va0, va1, vg, vu;
#define G1_LOAD(kb)                                                            \
    do {                                                                       \
        va0 = *(const float4*)(Arow + (kb) + acq);                             \
        va1 = *(const float4*)(Arow + (kb) + acq + 4);                         \
        vg  = *(const float4*)(Wg + (size_t)((kb) + bk) * ID + ncol0 + bn);    \
        vu  = *(const float4*)(Wu + (size_t)((kb) + bk) * ID + ncol0 + bn);    \
    } while (0)

#define G1_STORE(s)                                                            \
    do {                                                                       \
        float av[8] = {va0.x, va0.y, va0.z, va0.w, va1.x, va1.y, va1.z, va1.w};\
        _Pragma("unroll")                                                      \
        for (int q = 0; q < 4; q++) {                                          \
            float v0 = av[q * 2], v1 = av[q * 2 + 1];                          \
            __nv_bfloat16 h0 = __float2bfloat16(v0);                           \
            __nv_bfloat16 h1 = __float2bfloat16(v1);                           \
            __nv_bfloat16 l0 = __float2bfloat16(v0 - __bfloat162float(h0));    \
            __nv_bfloat16 l1 = __float2bfloat16(v1 - __bfloat162float(h1));    \
            *(uint32_t*)&sAh[s][ar * RS + acq + q * 2] = packbf(h0, h1);       \
            *(uint32_t*)&sAl[s][ar * RS + acq + q * 2] = packbf(l0, l1);       \
        }                                                                      \
        float gv[4] = {vg.x, vg.y, vg.z, vg.w};                                \
        float uv[4] = {vu.x, vu.y, vu.z, vu.w};                                \
        _Pragma("unroll")                                                      \
        for (int j = 0; j < 4; j++) {                                          \
            int n = bn + j;                                                    \
            __nv_bfloat16 h = __float2bfloat16(gv[j]);                         \
            sGh[s][n * RS + bk] = h;                                           \
            sGl[s][n * RS + bk] = __float2bfloat16(gv[j] - __bfloat162float(h));\
            __nv_bfloat16 h2 = __float2bfloat16(uv[j]);                        \
            sUh[s][n * RS + bk] = h2;                                          \
            sUl[s][n * RS + bk] = __float2bfloat16(uv[j] - __bfloat162float(h2));\
        }                                                                      \
    } while (0)

    float accg[2][4][4] = {};
    float accu[2][4][4] = {};

    const int NCH = HD / 16;
    G1_LOAD(0);
    G1_STORE(0);
    G1_LOAD(16);
    __syncthreads();

    for (int ch = 0; ch < NCH; ch++) {
        const int cur = ch & 1, nxt = cur ^ 1;
        if (ch + 1 < NCH) G1_STORE(nxt);              // regs hold chunk ch+1
        if (ch + 2 < NCH) G1_LOAD((ch + 2) * 16);     // overlaps MMAs

        uint32_t afh[2][4], afl[2][4];
#pragma unroll
        for (int am = 0; am < 2; am++) {
            int r = wm * 32 + am * 16 + (lane >> 2);
            int c = (lane & 3) * 2;
            afh[am][0] = *(const uint32_t*)&sAh[cur][r * RS + c];
            afh[am][1] = *(const uint32_t*)&sAh[cur][(r + 8) * RS + c];
            afh[am][2] = *(const uint32_t*)&sAh[cur][r * RS + c + 8];
            afh[am][3] = *(const uint32_t*)&sAh[cur][(r + 8) * RS + c + 8];
            afl[am][0] = *(const uint32_t*)&sAl[cur][r * RS + c];
            afl[am][1] = *(const uint32_t*)&sAl[cur][(r + 8) * RS + c];
            afl[am][2] = *(const uint32_t*)&sAl[cur][r * RS + c + 8];
            afl[am][3] = *(const uint32_t*)&sAl[cur][(r + 8) * RS + c + 8];
        }
#pragma unroll
        for (int an = 0; an < 4; an++) {
            int n = wn * 32 + an * 8 + (lane >> 2);
            int c = (lane & 3) * 2;
            uint32_t bh[2], bl[2], uh[2], ul[2];
            bh[0] = *(const uint32_t*)&sGh[cur][n * RS + c];
            bh[1] = *(const uint32_t*)&sGh[cur][n * RS + c + 8];
            bl[0] = *(const uint32_t*)&sGl[cur][n * RS + c];
            bl[1] = *(const uint32_t*)&sGl[cur][n * RS + c + 8];
            uh[0] = *(const uint32_t*)&sUh[cur][n * RS + c];
            uh[1] = *(const uint32_t*)&sUh[cur][n * RS + c + 8];
            ul[0] = *(const uint32_t*)&sUl[cur][n * RS + c];
            ul[1] = *(const uint32_t*)&sUl[cur][n * RS + c + 8];
#pragma unroll
            for (int am = 0; am < 2; am++) {
                mma16816(accg[am][an], afh[am], bh);
                mma16816(accg[am][an], afh[am], bl);
                mma16816(accg[am][an], afl[am], bh);
                mma16816(accu[am][an], afh[am], uh);
                mma16816(accu[am][an], afh[am], ul);
                mma16816(accu[am][an], afl[am], uh);
            }
        }
        __syncthreads();
    }
#undef G1_LOAD
#undef G1_STORE

    // epilogue: silu(g)*u -> fp32 g_act (sorted order for routed)
    const int obase = (ROUTED ? row_off : 0) + mtile * 128;
#pragma unroll
    for (int am = 0; am < 2; am++)
#pragma unroll
        for (int an = 0; an < 4; an++) {
            int rl0 = wm * 32 + am * 16 + (lane >> 2);
            int col = ncol0 + wn * 32 + an * 8 + (lane & 3) * 2;
#pragma unroll
            for (int h = 0; h < 2; h++) {
                int rl = rl0 + h * 8;
                if (mtile * 128 + rl < rows) {
                    float g0 = accg[am][an][h * 2], g1 = accg[am][an][h * 2 + 1];
                    float u0 = accu[am][an][h * 2], u1 = accu[am][an][h * 2 + 1];
                    float v0 = g0 / (1.f + __expf(-g0)) * u0;
                    float v1 = g1 / (1.f + __expf(-g1)) * u1;
                    *(float2*)(g_act + (size_t)(obase + rl) * ID + col) =
                        make_float2(v0, v1);
                }
            }
        }
}

// ---------------- GEMM2: out (+)= act @ Wd -----------------------------------
// Tile M=128 x N=128, K-chunk 16, double-buffered (48KB static smem).
template <bool ROUTED>
__global__ void __launch_bounds__(256) gemm2_mma(const float* __restrict__ Wd_all,
                                                 float* __restrict__ out) {
    const int e       = ROUTED ? blockIdx.z : 0;
    const int rows    = ROUTED ? g_counts[e] : TOK;
    const int row_off = ROUTED ? g_offsets[e] : 0;
    const int mtile   = blockIdx.y;
    if (mtile * 128 >= rows) return;
    const int ncol0 = blockIdx.x * 128;

    __shared__ __align__(16) __nv_bfloat16 sAh[2][128 * RS];
    __shared__ __align__(16) __nv_bfloat16 sAl[2][128 * RS];
    __shared__ __align__(16) __nv_bfloat16 sWh[2][128 * RS];
    __shared__ __align__(16) __nv_bfloat16 sWl[2][128 * RS];

    const int tid = threadIdx.x, wid = tid >> 5, lane = tid & 31;
    const int wm = wid >> 1, wn = wid & 1;

    const int ar  = tid >> 1;
    const int acq = (tid & 1) * 8;
    const int abase = (ROUTED ? row_off : 0) + mtile * 128;
    const float* Arow = g_act + (size_t)(abase + ar) * ID;

    const int bk = tid & 15;
    const int bn = (tid >> 4) * 8;
    const float* Wd = Wd_all + (ROUTED ? (size_t)e * ID * HD : 0);

    float4 va0, va1, vw0, vw1;
#define G2_LOAD(kb)                                                            \
    do {                                                                       \
        va0 = *(const float4*)(Arow + (kb) + acq);                             \
        va1 = *(const float4*)(Arow + (kb) + acq + 4);                         \
        const float* wdp = Wd + (size_t)((kb) + bk) * HD + ncol0 + bn;         \
        vw0 = *(const float4*)(wdp);                                           \
        vw1 = *(const float4*)(wdp + 4);                                       \
    } while (0)

#define G2_STORE(s)                                                            \
    do {                                                                       \
        float av[8] = {va0.x, va0.y, va0.z, va0.w, va1.x, va1.y, va1.z, va1.w};\
        _Pragma("unroll")                                                      \
        for (int q = 0; q < 4; q++) {                                          \
            float v0 = av[q * 2], v1 = av[q * 2 + 1];                          \
            __nv_bfloat16 h0 = __float2bfloat16(v0);                           \
            __nv_bfloat16 h1 = __float2bfloat16(v1);                           \
            __nv_bfloat16 l0 = __float2bfloat16(v0 - __bfloat162float(h0));    \
            __nv_bfloat16 l1 = __float2bfloat16(v1 - __bfloat162float(h1));    \
            *(uint32_t*)&sAh[s][ar * RS + acq + q * 2] = packbf(h0, h1);       \
            *(uint32_t*)&sAl[s][ar * RS + acq + q * 2] = packbf(l0, l1);       \
        }                                                                      \
        float wv[8] = {vw0.x, vw0.y, vw0.z, vw0.w, vw1.x, vw1.y, vw1.z, vw1.w};\
        _Pragma("unroll")                                                      \
        for (int j = 0; j < 8; j++) {                                          \
            int n = bn + j;                                                    \
            __nv_bfloat16 h = __float2bfloat16(wv[j]);                         \
            sWh[s][n * RS + bk] = h;                                           \
            sWl[s][n * RS + bk] = __float2bfloat16(wv[j] - __bfloat162float(h));\
        }                                                                      \
    } while (0)

    float acc[2][8][4] = {};

    const int NCH = ID / 16;
    G2_LOAD(0);
    G2_STORE(0);
    G2_LOAD(16);
    __syncthreads();

    for (int ch = 0; ch < NCH; ch++) {
        const int cur = ch & 1, nxt = cur ^ 1;
        if (ch + 1 < NCH) G2_STORE(nxt);
        if (ch + 2 < NCH) G2_LOAD((ch + 2) * 16);

        uint32_t afh[2][4], afl[2][4];
#pragma unroll
        for (int am = 0; am < 2; am++) {
            int r = wm * 32 + am * 16 + (lane >> 2);
            int c = (lane & 3) * 2;
            afh[am][0] = *(const uint32_t*)&sAh[cur][r * RS + c];
            afh[am][1] = *(const uint32_t*)&sAh[cur][(r + 8) * RS + c];
            afh[am][2] = *(const uint32_t*)&sAh[cur][r * RS + c + 8];
            afh[am][3] = *(const uint32_t*)&sAh[cur][(r + 8) * RS + c + 8];
            afl[am][0] = *(const uint32_t*)&sAl[cur][r * RS + c];
            afl[am][1] = *(const uint32_t*)&sAl[cur][(r + 8) * RS + c];
            afl[am][2] = *(const uint32_t*)&sAl[cur][r * RS + c + 8];
            afl[am][3] = *(const uint32_t*)&sAl[cur][(r + 8) * RS + c + 8];
        }
#pragma unroll
        for (int an = 0; an < 8; an++) {
            int n = wn * 64 + an * 8 + (lane >> 2);
            int c = (lane & 3) * 2;
            uint32_t bh[2], bl[2];
            bh[0] = *(const uint32_t*)&sWh[cur][n * RS + c];
            bh[1] = *(const uint32_t*)&sWh[cur][n * RS + c + 8];
            bl[0] = *(const uint32_t*)&sWl[cur][n * RS + c];
            bl[1] = *(const uint32_t*)&sWl[cur][n * RS + c + 8];
#pragma unroll
            for (int am = 0; am < 2; am++) {
                mma16816(acc[am][an], afh[am], bh);
                mma16816(acc[am][an], afh[am], bl);
                mma16816(acc[am][an], afl[am], bh);
            }
        }
        __syncthreads();
    }
#undef G2_LOAD
#undef G2_STORE

    // epilogue: write/accumulate fp32 output per token
#pragma unroll
    for (int am = 0; am < 2; am++)
#pragma unroll
        for (int an = 0; an < 8; an++) {
            int rl0 = wm * 32 + am * 16 + (lane >> 2);
            int col = ncol0 + wn * 64 + an * 8 + (lane & 3) * 2;
#pragma unroll
            for (int h = 0; h < 2; h++) {
                int rl = rl0 + h * 8;
                int r = mtile * 128 + rl;
                if (r < rows) {
                    int token = ROUTED ? g_sorted[row_off + r] : r;
                    float* po = out + (size_t)token * HD + col;
                    float v0 = acc[am][an][h * 2], v1 = acc[am][an][h * 2 + 1];
                    if (ROUTED) {
                        float2 o2 = *(float2*)po;
                        v0 += o2.x; v1 += o2.y;
                    }
                    *(float2*)po = make_float2(v0, v1);
                }
            }
        }
}

// ---------------- launch -----------------------------------------------------
extern "C" void kernel_launch(void* const* d_in, const int* in_sizes, int n_in,
                              void* d_out, int out_size) {
    (void)in_sizes; (void)n_in; (void)out_size;
    const float* x       = (const float*)d_in[0];
    const float* gate_w  = (const float*)d_in[1];
    const float* sh_gate = (const float*)d_in[2];
    const float* sh_up   = (const float*)d_in[3];
    const float* sh_down = (const float*)d_in[4];
    const float* rt_gate = (const float*)d_in[5];
    const float* rt_up   = (const float*)d_in[6];
    const float* rt_down = (const float*)d_in[7];
    float* out = (float*)d_out;

    // routing
    init_kernel<<<1, 32>>>();
    router_kernel<<<TOK / 8, 256>>>(x, gate_w);
    scan_kernel<<<1, 32>>>();
    build_sorted_kernel<<<TOK / 256, 256>>>();

    // shared expert first (act buffer reuse; writes full out, covers poison)
    gemm1_mma<false><<<dim3(ID / 64, TOK / 128, 1), 256>>>(x, sh_gate, sh_up);
    gemm2_mma<false><<<dim3(HD / 128, TOK / 128, 1), 256>>>(sh_down, out);

    // routed experts (scatter-add into out)
    gemm1_mma<true><<<dim3(ID / 64, TOK / 128, NE), 256>>>(x, rt_gate, rt_up);
    gemm2_mma<true><<<dim3(HD / 128, TOK / 128, NE), 256>>>(rt_down, out);
}

// round 8
// speedup vs baseline: 2.8487x; 1.1783x over previous
#include <cuda_runtime.h>
#include <cuda_bf16.h>
#include <math.h>
#include <stdint.h>

#define TOK 2048
#define HD  1024
#define ID  2048
#define NE  8
#define PAD 128
#define RS  24   // smem row stride in bf16 elems (48B): conflict-free frags + ldsm

// ---------------- scratch (device globals; keep SMALL — proven safe) --------
__device__ __align__(256) float g_xs[(size_t)TOK * HD];          // score-scaled tokens
__device__ __align__(256) float g_act[(size_t)(TOK + PAD) * ID]; // activations fp32
__device__ int g_expert[TOK];
__device__ int g_counts[NE];
__device__ int g_offsets[NE];
__device__ int g_cursor[NE];
__device__ int g_sorted[TOK];

// ---------------- helpers ----------------------------------------------------
__device__ __forceinline__ void mma16816(float* d, const uint32_t* a, const uint32_t* b) {
    asm volatile(
        "mma.sync.aligned.m16n8k16.row.col.f32.bf16.bf16.f32 "
        "{%0,%1,%2,%3}, {%4,%5,%6,%7}, {%8,%9}, {%0,%1,%2,%3};"
        : "+f"(d[0]), "+f"(d[1]), "+f"(d[2]), "+f"(d[3])
        : "r"(a[0]), "r"(a[1]), "r"(a[2]), "r"(a[3]), "r"(b[0]), "r"(b[1]));
}
__device__ __forceinline__ void ldsm4(uint32_t* r, const void* p) {
    uint32_t a = (uint32_t)__cvta_generic_to_shared(p);
    asm volatile("ldmatrix.sync.aligned.m8n8.x4.shared.b16 {%0,%1,%2,%3}, [%4];"
                 : "=r"(r[0]), "=r"(r[1]), "=r"(r[2]), "=r"(r[3]) : "r"(a));
}
__device__ __forceinline__ uint32_t packbf(__nv_bfloat16 a, __nv_bfloat16 b) {
    __nv_bfloat162 t; t.x = a; t.y = b;
    return reinterpret_cast<uint32_t&>(t);
}

// ---------------- small kernels (identical to passing R1/R6/R7) --------------
__global__ void init_kernel() {
    if (threadIdx.x < NE) g_counts[threadIdx.x] = 0;
}

__global__ void router_kernel(const float* __restrict__ x,
                              const float* __restrict__ gate_w) {
    int warp = (blockIdx.x * blockDim.x + threadIdx.x) >> 5;
    int lane = threadIdx.x & 31;
    if (warp >= TOK) return;
    const float* xr = x + (size_t)warp * HD;
    float acc[NE];
#pragma unroll
    for (int e = 0; e < NE; e++) acc[e] = 0.f;
    for (int h = lane; h < HD; h += 32) {
        float xv = xr[h];
        const float* w = gate_w + (size_t)h * NE;
#pragma unroll
        for (int e = 0; e < NE; e++) acc[e] = fmaf(xv, w[e], acc[e]);
    }
#pragma unroll
    for (int e = 0; e < NE; e++) {
#pragma unroll
        for (int o = 16; o > 0; o >>= 1)
            acc[e] += __shfl_xor_sync(0xffffffffu, acc[e], o);
    }
    int best = 0; float bv = acc[0];
#pragma unroll
    for (int e = 1; e < NE; e++) if (acc[e] > bv) { bv = acc[e]; best = e; }
    float score = 1.f / (1.f + expf(-bv));
    if (lane == 0) {
        g_expert[warp] = best;
        atomicAdd(&g_counts[best], 1);
    }
    float* dst = g_xs + (size_t)warp * HD;
    for (int h = lane; h < HD; h += 32) dst[h] = xr[h] * score;
}

__global__ void scan_kernel() {
    if (threadIdx.x == 0) {
        int off = 0;
        for (int e = 0; e < NE; e++) {
            g_offsets[e] = off;
            g_cursor[e]  = off;
            off += g_counts[e];
        }
    }
}

__global__ void build_sorted_kernel() {
    int t = blockIdx.x * blockDim.x + threadIdx.x;
    if (t >= TOK) return;
    int e = g_expert[t];
    int pos = atomicAdd(&g_cursor[e], 1);
    g_sorted[pos] = t;
}

// ---------------- GEMM1: act = silu(A@Wg)*(A@Wu) -----------------------------
// Tile M=128 x N=64, K-chunk 16, double-buffered (48KB static smem), ldmatrix.
template <bool ROUTED>
__global__ void __launch_bounds__(256) gemm1_mma(const float* __restrict__ xin,
                                                 const float* __restrict__ Wg_all,
                                                 const float* __restrict__ Wu_all) {
    const int e       = ROUTED ? blockIdx.z : 0;
    const int rows    = ROUTED ? g_counts[e] : TOK;
    const int row_off = ROUTED ? g_offsets[e] : 0;
    const int mtile   = blockIdx.y;
    if (mtile * 128 >= rows) return;
    const int ncol0 = blockIdx.x * 64;

    __shared__ __align__(16) __nv_bfloat16 sAh[2][128 * RS];
    __shared__ __align__(16) __nv_bfloat16 sAl[2][128 * RS];
    __shared__ __align__(16) __nv_bfloat16 sGh[2][64 * RS];
    __shared__ __align__(16) __nv_bfloat16 sGl[2][64 * RS];
    __shared__ __align__(16) __nv_bfloat16 sUh[2][64 * RS];
    __shared__ __align__(16) __nv_bfloat16 sUl[2][64 * RS];

    const int tid = threadIdx.x, wid = tid >> 5, lane = tid & 31;
    const int wm = wid >> 1, wn = wid & 1;

    // ldmatrix lane offsets (element index into a tile with row stride RS)
    const int a_off = (wm * 32 + (lane & 7) + ((lane >> 3) & 1) * 8) * RS + (lane >> 4) * 8;
    const int b_off = (wn * 32 + (lane & 7) + (lane >> 4) * 8) * RS + ((lane >> 3) & 1) * 8;

    // A loader: row ar (0..127), 8 fp32 cols at acq
    const int ar  = tid >> 1;
    const int acq = (tid & 1) * 8;
    const float* Arow;
    if (ROUTED) {
        int sr = row_off + mtile * 128 + ar;
        sr = sr < TOK ? sr : TOK - 1;           // clamp (masked in epilogue)
        Arow = g_xs + (size_t)g_sorted[sr] * HD;
    } else {
        Arow = xin + (size_t)(mtile * 128 + ar) * HD;
    }
    // B loader: k = bk (0..15), 4 n at bn
    const int bk = tid & 15;
    const int bn = (tid >> 4) * 4;
    const float* Wg = Wg_all + (ROUTED ? (size_t)e * HD * ID : 0);
    const float* Wu = Wu_all + (ROUTED ? (size_t)e * HD * ID : 0);

    float4 va0, va1, vg, vu;
#define G1_LOAD(kb)                                                            \
    do {                                                                       \
        va0 = *(const float4*)(Arow + (kb) + acq);                             \
        va1 = *(const float4*)(Arow + (kb) + acq + 4);                         \
        vg  = *(const float4*)(Wg + (size_t)((kb) + bk) * ID + ncol0 + bn);    \
        vu  = *(const float4*)(Wu + (size_t)((kb) + bk) * ID + ncol0 + bn);    \
    } while (0)

#define G1_STORE(s)                                                            \
    do {                                                                       \
        float av[8] = {va0.x, va0.y, va0.z, va0.w, va1.x, va1.y, va1.z, va1.w};\
        uint4 ph, pl;                                                          \
        {                                                                      \
            __nv_bfloat16 h[8], l[8];                                          \
            _Pragma("unroll")                                                  \
            for (int q = 0; q < 8; q++) {                                      \
                h[q] = __float2bfloat16(av[q]);                                \
                l[q] = __float2bfloat16(av[q] - __bfloat162float(h[q]));       \
            }                                                                  \
            ph.x = packbf(h[0], h[1]); ph.y = packbf(h[2], h[3]);              \
            ph.z = packbf(h[4], h[5]); ph.w = packbf(h[6], h[7]);              \
            pl.x = packbf(l[0], l[1]); pl.y = packbf(l[2], l[3]);              \
            pl.z = packbf(l[4], l[5]); pl.w = packbf(l[6], l[7]);              \
        }                                                                      \
        *(uint4*)&sAh[s][ar * RS + acq] = ph;                                  \
        *(uint4*)&sAl[s][ar * RS + acq] = pl;                                  \
        float gv[4] = {vg.x, vg.y, vg.z, vg.w};                                \
        float uv[4] = {vu.x, vu.y, vu.z, vu.w};                                \
        _Pragma("unroll")                                                      \
        for (int j = 0; j < 4; j++) {                                          \
            int n = bn + j;                                                    \
            __nv_bfloat16 h = __float2bfloat16(gv[j]);                         \
            sGh[s][n * RS + bk] = h;                                           \
            sGl[s][n * RS + bk] = __float2bfloat16(gv[j] - __bfloat162float(h));\
            __nv_bfloat16 h2 = __float2bfloat16(uv[j]);                        \
            sUh[s][n * RS + bk] = h2;                                          \
            sUl[s][n * RS + bk] = __float2bfloat16(uv[j] - __bfloat162float(h2));\
        }                                                                      \
    } while (0)

    float accg[2][4][4] = {};
    float accu[2][4][4] = {};

    const int NCH = HD / 16;
    G1_LOAD(0);
    G1_STORE(0);
    G1_LOAD(16);
    __syncthreads();

    for (int ch = 0; ch < NCH; ch++) {
        const int cur = ch & 1, nxt = cur ^ 1;
        if (ch + 1 < NCH) G1_STORE(nxt);              // regs hold chunk ch+1
        if (ch + 2 < NCH) G1_LOAD((ch + 2) * 16);     // overlaps MMAs

        uint32_t afh[2][4], afl[2][4];
#pragma unroll
        for (int am = 0; am < 2; am++) {
            ldsm4(afh[am], &sAh[cur][a_off + am * 16 * RS]);
            ldsm4(afl[am], &sAl[cur][a_off + am * 16 * RS]);
        }
        uint32_t bgh[2][4], bgl[2][4], buh[2][4], bul[2][4];
#pragma unroll
        for (int anp = 0; anp < 2; anp++) {
            ldsm4(bgh[anp], &sGh[cur][b_off + anp * 16 * RS]);
            ldsm4(bgl[anp], &sGl[cur][b_off + anp * 16 * RS]);
            ldsm4(buh[anp], &sUh[cur][b_off + anp * 16 * RS]);
            ldsm4(bul[anp], &sUl[cur][b_off + anp * 16 * RS]);
        }
#pragma unroll
        for (int an = 0; an < 4; an++) {
            const uint32_t* bh = &bgh[an >> 1][(an & 1) * 2];
            const uint32_t* bl = &bgl[an >> 1][(an & 1) * 2];
            const uint32_t* uh = &buh[an >> 1][(an & 1) * 2];
            const uint32_t* ul = &bul[an >> 1][(an & 1) * 2];
#pragma unroll
            for (int am = 0; am < 2; am++) {
                mma16816(accg[am][an], afh[am], bh);
                mma16816(accg[am][an], afh[am], bl);
                mma16816(accg[am][an], afl[am], bh);
                mma16816(accu[am][an], afh[am], uh);
                mma16816(accu[am][an], afh[am], ul);
                mma16816(accu[am][an], afl[am], uh);
            }
        }
        __syncthreads();
    }
#undef G1_LOAD
#undef G1_STORE

    // epilogue: silu(g)*u -> fp32 g_act (sorted order for routed)
    const int obase = (ROUTED ? row_off : 0) + mtile * 128;
#pragma unroll
    for (int am = 0; am < 2; am++)
#pragma unroll
        for (int an = 0; an < 4; an++) {
            int rl0 = wm * 32 + am * 16 + (lane >> 2);
            int col = ncol0 + wn * 32 + an * 8 + (lane & 3) * 2;
#pragma unroll
            for (int h = 0; h < 2; h++) {
                int rl = rl0 + h * 8;
                if (mtile * 128 + rl < rows) {
                    float g0 = accg[am][an][h * 2], g1 = accg[am][an][h * 2 + 1];
                    float u0 = accu[am][an][h * 2], u1 = accu[am][an][h * 2 + 1];
                    float v0 = g0 / (1.f + __expf(-g0)) * u0;
                    float v1 = g1 / (1.f + __expf(-g1)) * u1;
                    *(float2*)(g_act + (size_t)(obase + rl) * ID + col) =
                        make_float2(v0, v1);
                }
            }
        }
}

// ---------------- GEMM2: out (+)= act @ Wd -----------------------------------
// Tile M=128 x N=128, K-chunk 16, double-buffered (48KB static smem), ldmatrix.
template <bool ROUTED>
__global__ void __launch_bounds__(256) gemm2_mma(const float* __restrict__ Wd_all,
                                                 float* __restrict__ out) {
    const int e       = ROUTED ? blockIdx.z : 0;
    const int rows    = ROUTED ? g_counts[e] : TOK;
    const int row_off = ROUTED ? g_offsets[e] : 0;
    const int mtile   = blockIdx.y;
    if (mtile * 128 >= rows) return;
    const int ncol0 = blockIdx.x * 128;

    __shared__ __align__(16) __nv_bfloat16 sAh[2][128 * RS];
    __shared__ __align__(16) __nv_bfloat16 sAl[2][128 * RS];
    __shared__ __align__(16) __nv_bfloat16 sWh[2][128 * RS];
    __shared__ __align__(16) __nv_bfloat16 sWl[2][128 * RS];

    const int tid = threadIdx.x, wid = tid >> 5, lane = tid & 31;
    const int wm = wid >> 1, wn = wid & 1;

    const int a_off = (wm * 32 + (lane & 7) + ((lane >> 3) & 1) * 8) * RS + (lane >> 4) * 8;
    const int b_off = (wn * 64 + (lane & 7) + (lane >> 4) * 8) * RS + ((lane >> 3) & 1) * 8;

    const int ar  = tid >> 1;
    const int acq = (tid & 1) * 8;
    const int abase = (ROUTED ? row_off : 0) + mtile * 128;
    const float* Arow = g_act + (size_t)(abase + ar) * ID;

    const int bk = tid & 15;
    const int bn = (tid >> 4) * 8;
    const float* Wd = Wd_all + (ROUTED ? (size_t)e * ID * HD : 0);

    float4 va0, va1, vw0, vw1;
#define G2_LOAD(kb)                                                            \
    do {                                                                       \
        va0 = *(const float4*)(Arow + (kb) + acq);                             \
        va1 = *(const float4*)(Arow + (kb) + acq + 4);                         \
        const float* wdp = Wd + (size_t)((kb) + bk) * HD + ncol0 + bn;         \
        vw0 = *(const float4*)(wdp);                                           \
        vw1 = *(const float4*)(wdp + 4);                                       \
    } while (0)

#define G2_STORE(s)                                                            \
    do {                                                                       \
        float av[8] = {va0.x, va0.y, va0.z, va0.w, va1.x, va1.y, va1.z, va1.w};\
        uint4 ph, pl;                                                          \
        {                                                                      \
            __nv_bfloat16 h[8], l[8];                                          \
            _Pragma("unroll")                                                  \
            for (int q = 0; q < 8; q++) {                                      \
                h[q] = __float2bfloat16(av[q]);                                \
                l[q] = __float2bfloat16(av[q] - __bfloat162float(h[q]));       \
            }                                                                  \
            ph.x = packbf(h[0], h[1]); ph.y = packbf(h[2], h[3]);              \
            ph.z = packbf(h[4], h[5]); ph.w = packbf(h[6], h[7]);              \
            pl.x = packbf(l[0], l[1]); pl.y = packbf(l[2], l[3]);              \
            pl.z = packbf(l[4], l[5]); pl.w = packbf(l[6], l[7]);              \
        }                                                                      \
        *(uint4*)&sAh[s][ar * RS + acq] = ph;                                  \
        *(uint4*)&sAl[s][ar * RS + acq] = pl;                                  \
        float wv[8] = {vw0.x, vw0.y, vw0.z, vw0.w, vw1.x, vw1.y, vw1.z, vw1.w};\
        _Pragma("unroll")                                                      \
        for (int j = 0; j < 8; j++) {                                          \
            int n = bn + j;                                                    \
            __nv_bfloat16 h = __float2bfloat16(wv[j]);                         \
            sWh[s][n * RS + bk] = h;                                           \
            sWl[s][n * RS + bk] = __float2bfloat16(wv[j] - __bfloat162float(h));\
        }                                                                      \
    } while (0)

    float acc[2][8][4] = {};

    const int NCH = ID / 16;
    G2_LOAD(0);
    G2_STORE(0);
    G2_LOAD(16);
    __syncthreads();

    for (int ch = 0; ch < NCH; ch++) {
        const int cur = ch & 1, nxt = cur ^ 1;
        if (ch + 1 < NCH) G2_STORE(nxt);
        if (ch + 2 < NCH) G2_LOAD((ch + 2) * 16);

        uint32_t afh[2][4], afl[2][4];
#pragma unroll
        for (int am = 0; am < 2; am++) {
            ldsm4(afh[am], &sAh[cur][a_off + am * 16 * RS]);
            ldsm4(afl[am], &sAl[cur][a_off + am * 16 * RS]);
        }
        uint32_t bwh[4][4], bwl[4][4];
#pragma unroll
        for (int anp = 0; anp < 4; anp++) {
            ldsm4(bwh[anp], &sWh[cur][b_off + anp * 16 * RS]);
            ldsm4(bwl[anp], &sWl[cur][b_off + anp * 16 * RS]);
        }
#pragma unroll
        for (int an = 0; an < 8; an++) {
            const uint32_t* bh = &bwh[an >> 1][(an & 1) * 2];
            const uint32_t* bl = &bwl[an >> 1][(an & 1) * 2];
#pragma unroll
            for (int am = 0; am < 2; am++) {
                mma16816(acc[am][an], afh[am], bh);
                mma16816(acc[am][an], afh[am], bl);
                mma16816(acc[am][an], afl[am], bh);
            }
        }
        __syncthreads();
    }
#undef G2_LOAD
#undef G2_STORE

    // epilogue: write/accumulate fp32 output per token
#pragma unroll
    for (int am = 0; am < 2; am++)
#pragma unroll
        for (int an = 0; an < 8; an++) {
            int rl0 = wm * 32 + am * 16 + (lane >> 2);
            int col = ncol0 + wn * 64 + an * 8 + (lane & 3) * 2;
#pragma unroll
            for (int h = 0; h < 2; h++) {
                int rl = rl0 + h * 8;
                int r = mtile * 128 + rl;
                if (r < rows) {
                    int token = ROUTED ? g_sorted[row_off + r] : r;
                    float* po = out + (size_t)token * HD + col;
                    float v0 = acc[am][an][h * 2], v1 = acc[am][an][h * 2 + 1];
                    if (ROUTED) {
                        float2 o2 = *(float2*)po;
                        v0 += o2.x; v1 += o2.y;
                    }
                    *(float2*)po = make_float2(v0, v1);
                }
            }
        }
}

// ---------------- launch -----------------------------------------------------
extern "C" void kernel_launch(void* const* d_in, const int* in_sizes, int n_in,
                              void* d_out, int out_size) {
    (void)in_sizes; (void)n_in; (void)out_size;
    const float* x       = (const float*)d_in[0];
    const float* gate_w  = (const float*)d_in[1];
    const float* sh_gate = (const float*)d_in[2];
    const float* sh_up   = (const float*)d_in[3];
    const float* sh_down = (const float*)d_in[4];
    const float* rt_gate = (const float*)d_in[5];
    const float* rt_up   = (const float*)d_in[6];
    const float* rt_down = (const float*)d_in[7];
    float* out = (float*)d_out;

    // routing
    init_kernel<<<1, 32>>>();
    router_kernel<<<TOK / 8, 256>>>(x, gate_w);
    scan_kernel<<<1, 32>>>();
    build_sorted_kernel<<<TOK / 256, 256>>>();

    // shared expert first (act buffer reuse; writes full out, covers poison)
    gemm1_mma<false><<<dim3(ID / 64, TOK / 128, 1), 256>>>(x, sh_gate, sh_up);
    gemm2_mma<false><<<dim3(HD / 128, TOK / 128, 1), 256>>>(sh_down, out);

    // routed experts (scatter-add into out)
    gemm1_mma<true><<<dim3(ID / 64, TOK / 128, NE), 256>>>(x, rt_gate, rt_up);
    gemm2_mma<true><<<dim3(HD / 128, TOK / 128, NE), 256>>>(rt_down, out);
}

// round 9
// speedup vs baseline: 3.3459x; 1.1745x over previous
#include <cuda_runtime.h>
#include <cuda_bf16.h>
#include <math.h>
#include <stdint.h>

#define TOK 2048
#define HD  1024
#define ID  2048
#define NE  8
#define PAD 128
#define RS   24   // A smem row stride (elems): conflict-free ldsm + frags
#define RSB1 72   // gemm1 B smem row stride [k][n] (64 n + 8 pad)
#define RSB2 136  // gemm2 B smem row stride [k][n] (128 n + 8 pad)

// ---------------- scratch (device globals; keep SMALL — proven safe) --------
__device__ __align__(256) float g_xs[(size_t)TOK * HD];          // score-scaled tokens
__device__ __align__(256) float g_act[(size_t)(TOK + PAD) * ID]; // activations fp32
__device__ int g_expert[TOK];
__device__ int g_counts[NE];
__device__ int g_offsets[NE];
__device__ int g_cursor[NE];
__device__ int g_sorted[TOK];

// ---------------- helpers ----------------------------------------------------
__device__ __forceinline__ void mma16816(float* d, const uint32_t* a, const uint32_t* b) {
    asm volatile(
        "mma.sync.aligned.m16n8k16.row.col.f32.bf16.bf16.f32 "
        "{%0,%1,%2,%3}, {%4,%5,%6,%7}, {%8,%9}, {%0,%1,%2,%3};"
        : "+f"(d[0]), "+f"(d[1]), "+f"(d[2]), "+f"(d[3])
        : "r"(a[0]), "r"(a[1]), "r"(a[2]), "r"(a[3]), "r"(b[0]), "r"(b[1]));
}
__device__ __forceinline__ void ldsm4(uint32_t* r, const void* p) {
    uint32_t a = (uint32_t)__cvta_generic_to_shared(p);
    asm volatile("ldmatrix.sync.aligned.m8n8.x4.shared.b16 {%0,%1,%2,%3}, [%4];"
                 : "=r"(r[0]), "=r"(r[1]), "=r"(r[2]), "=r"(r[3]) : "r"(a));
}
__device__ __forceinline__ void ldsm4t(uint32_t* r, const void* p) {
    uint32_t a = (uint32_t)__cvta_generic_to_shared(p);
    asm volatile("ldmatrix.sync.aligned.m8n8.x4.trans.shared.b16 {%0,%1,%2,%3}, [%4];"
                 : "=r"(r[0]), "=r"(r[1]), "=r"(r[2]), "=r"(r[3]) : "r"(a));
}
// hi split by truncation: upper 16 bits of fp32 == bf16 (round-toward-zero)
__device__ __forceinline__ uint32_t hi2(float a, float b) {
    return __byte_perm(__float_as_uint(a), __float_as_uint(b), 0x7632);
}
__device__ __forceinline__ float hif(float a) {
    return __uint_as_float(__float_as_uint(a) & 0xFFFF0000u);
}
__device__ __forceinline__ uint32_t lo2(float a, float b) {
    __nv_bfloat162 t = __floats2bfloat162_rn(a - hif(a), b - hif(b));
    return reinterpret_cast<uint32_t&>(t);
}

// ---------------- small kernels (identical to passing R1/R6-R8) --------------
__global__ void init_kernel() {
    if (threadIdx.x < NE) g_counts[threadIdx.x] = 0;
}

__global__ void router_kernel(const float* __restrict__ x,
                              const float* __restrict__ gate_w) {
    int warp = (blockIdx.x * blockDim.x + threadIdx.x) >> 5;
    int lane = threadIdx.x & 31;
    if (warp >= TOK) return;
    const float* xr = x + (size_t)warp * HD;
    float acc[NE];
#pragma unroll
    for (int e = 0; e < NE; e++) acc[e] = 0.f;
    for (int h = lane; h < HD; h += 32) {
        float xv = xr[h];
        const float* w = gate_w + (size_t)h * NE;
#pragma unroll
        for (int e = 0; e < NE; e++) acc[e] = fmaf(xv, w[e], acc[e]);
    }
#pragma unroll
    for (int e = 0; e < NE; e++) {
#pragma unroll
        for (int o = 16; o > 0; o >>= 1)
            acc[e] += __shfl_xor_sync(0xffffffffu, acc[e], o);
    }
    int best = 0; float bv = acc[0];
#pragma unroll
    for (int e = 1; e < NE; e++) if (acc[e] > bv) { bv = acc[e]; best = e; }
    float score = 1.f / (1.f + expf(-bv));
    if (lane == 0) {
        g_expert[warp] = best;
        atomicAdd(&g_counts[best], 1);
    }
    float* dst = g_xs + (size_t)warp * HD;
    for (int h = lane; h < HD; h += 32) dst[h] = xr[h] * score;
}

__global__ void scan_kernel() {
    if (threadIdx.x == 0) {
        int off = 0;
        for (int e = 0; e < NE; e++) {
            g_offsets[e] = off;
            g_cursor[e]  = off;
            off += g_counts[e];
        }
    }
}

__global__ void build_sorted_kernel() {
    int t = blockIdx.x * blockDim.x + threadIdx.x;
    if (t >= TOK) return;
    int e = g_expert[t];
    int pos = atomicAdd(&g_cursor[e], 1);
    g_sorted[pos] = t;
}

// ---------------- GEMM1: act = silu(A@Wg)*(A@Wu) -----------------------------
// Tile M=128 x N=64, K-chunk 16, double-buffered. A smem [m][k]; B smem [k][n]
// with ldmatrix.trans fragments; truncation hi/lo split.
template <bool ROUTED>
__global__ void __launch_bounds__(256) gemm1_mma(const float* __restrict__ xin,
                                                 const float* __restrict__ Wg_all,
                                                 const float* __restrict__ Wu_all) {
    const int e       = ROUTED ? blockIdx.z : 0;
    const int rows    = ROUTED ? g_counts[e] : TOK;
    const int row_off = ROUTED ? g_offsets[e] : 0;
    const int mtile   = blockIdx.y;
    if (mtile * 128 >= rows) return;
    const int ncol0 = blockIdx.x * 64;

    __shared__ __align__(16) __nv_bfloat16 sAh[2][128 * RS];
    __shared__ __align__(16) __nv_bfloat16 sAl[2][128 * RS];
    __shared__ __align__(16) __nv_bfloat16 sGh[2][16 * RSB1];
    __shared__ __align__(16) __nv_bfloat16 sGl[2][16 * RSB1];
    __shared__ __align__(16) __nv_bfloat16 sUh[2][16 * RSB1];
    __shared__ __align__(16) __nv_bfloat16 sUl[2][16 * RSB1];

    const int tid = threadIdx.x, wid = tid >> 5, lane = tid & 31;
    const int wm = wid >> 1, wn = wid & 1;

    // ldmatrix lane offsets
    const int a_off = (wm * 32 + (lane & 7) + ((lane >> 3) & 1) * 8) * RS + (lane >> 4) * 8;
    const int b_off = (lane & 15) * RSB1 + (lane >> 4) * 8;   // trans: k row, n col

    // A loader: row ar (0..127), 8 fp32 cols at acq
    const int ar  = tid >> 1;
    const int acq = (tid & 1) * 8;
    const float* Arow;
    if (ROUTED) {
        int sr = row_off + mtile * 128 + ar;
        sr = sr < TOK ? sr : TOK - 1;           // clamp (masked in epilogue)
        Arow = g_xs + (size_t)g_sorted[sr] * HD;
    } else {
        Arow = xin + (size_t)(mtile * 128 + ar) * HD;
    }
    // B loader: k = bk (0..15), 4 n at bn4
    const int bk  = tid >> 4;
    const int bn4 = (tid & 15) * 4;
    const float* Wg = Wg_all + (ROUTED ? (size_t)e * HD * ID : 0);
    const float* Wu = Wu_all + (ROUTED ? (size_t)e * HD * ID : 0);

    float4 va0, va1, vg, vu;
#define G1_LOAD(kb)                                                            \
    do {                                                                       \
        va0 = *(const float4*)(Arow + (kb) + acq);                             \
        va1 = *(const float4*)(Arow + (kb) + acq + 4);                         \
        vg  = *(const float4*)(Wg + (size_t)((kb) + bk) * ID + ncol0 + bn4);   \
        vu  = *(const float4*)(Wu + (size_t)((kb) + bk) * ID + ncol0 + bn4);   \
    } while (0)

#define G1_STORE(s)                                                            \
    do {                                                                       \
        uint4 ph, pl;                                                          \
        ph.x = hi2(va0.x, va0.y); ph.y = hi2(va0.z, va0.w);                    \
        ph.z = hi2(va1.x, va1.y); ph.w = hi2(va1.z, va1.w);                    \
        pl.x = lo2(va0.x, va0.y); pl.y = lo2(va0.z, va0.w);                    \
        pl.z = lo2(va1.x, va1.y); pl.w = lo2(va1.z, va1.w);                    \
        *(uint4*)&sAh[s][ar * RS + acq] = ph;                                  \
        *(uint4*)&sAl[s][ar * RS + acq] = pl;                                  \
        *(uint2*)&sGh[s][bk * RSB1 + bn4] =                                    \
            make_uint2(hi2(vg.x, vg.y), hi2(vg.z, vg.w));                      \
        *(uint2*)&sGl[s][bk * RSB1 + bn4] =                                    \
            make_uint2(lo2(vg.x, vg.y), lo2(vg.z, vg.w));                      \
        *(uint2*)&sUh[s][bk * RSB1 + bn4] =                                    \
            make_uint2(hi2(vu.x, vu.y), hi2(vu.z, vu.w));                      \
        *(uint2*)&sUl[s][bk * RSB1 + bn4] =                                    \
            make_uint2(lo2(vu.x, vu.y), lo2(vu.z, vu.w));                      \
    } while (0)

    float accg[2][4][4] = {};
    float accu[2][4][4] = {};

    const int NCH = HD / 16;
    G1_LOAD(0);
    G1_STORE(0);
    G1_LOAD(16);
    __syncthreads();

    for (int ch = 0; ch < NCH; ch++) {
        const int cur = ch & 1, nxt = cur ^ 1;
        if (ch + 1 < NCH) G1_STORE(nxt);              // regs hold chunk ch+1
        if (ch + 2 < NCH) G1_LOAD((ch + 2) * 16);     // overlaps MMAs

        uint32_t afh[2][4], afl[2][4];
#pragma unroll
        for (int am = 0; am < 2; am++) {
            ldsm4(afh[am], &sAh[cur][a_off + am * 16 * RS]);
            ldsm4(afl[am], &sAl[cur][a_off + am * 16 * RS]);
        }
        uint32_t bgh[2][4], bgl[2][4], buh[2][4], bul[2][4];
#pragma unroll
        for (int p = 0; p < 2; p++) {
            int nofs = wn * 32 + p * 16;
            ldsm4t(bgh[p], &sGh[cur][b_off + nofs]);
            ldsm4t(bgl[p], &sGl[cur][b_off + nofs]);
            ldsm4t(buh[p], &sUh[cur][b_off + nofs]);
            ldsm4t(bul[p], &sUl[cur][b_off + nofs]);
        }
#pragma unroll
        for (int an = 0; an < 4; an++) {
            const uint32_t* bh = &bgh[an >> 1][(an & 1) * 2];
            const uint32_t* bl = &bgl[an >> 1][(an & 1) * 2];
            const uint32_t* uh = &buh[an >> 1][(an & 1) * 2];
            const uint32_t* ul = &bul[an >> 1][(an & 1) * 2];
#pragma unroll
            for (int am = 0; am < 2; am++) {
                mma16816(accg[am][an], afh[am], bh);
                mma16816(accg[am][an], afh[am], bl);
                mma16816(accg[am][an], afl[am], bh);
                mma16816(accu[am][an], afh[am], uh);
                mma16816(accu[am][an], afh[am], ul);
                mma16816(accu[am][an], afl[am], uh);
            }
        }
        __syncthreads();
    }
#undef G1_LOAD
#undef G1_STORE

    // epilogue: silu(g)*u -> fp32 g_act (sorted order for routed)
    const int obase = (ROUTED ? row_off : 0) + mtile * 128;
#pragma unroll
    for (int am = 0; am < 2; am++)
#pragma unroll
        for (int an = 0; an < 4; an++) {
            int rl0 = wm * 32 + am * 16 + (lane >> 2);
            int col = ncol0 + wn * 32 + an * 8 + (lane & 3) * 2;
#pragma unroll
            for (int h = 0; h < 2; h++) {
                int rl = rl0 + h * 8;
                if (mtile * 128 + rl < rows) {
                    float g0 = accg[am][an][h * 2], g1 = accg[am][an][h * 2 + 1];
                    float u0 = accu[am][an][h * 2], u1 = accu[am][an][h * 2 + 1];
                    float v0 = g0 / (1.f + __expf(-g0)) * u0;
                    float v1 = g1 / (1.f + __expf(-g1)) * u1;
                    *(float2*)(g_act + (size_t)(obase + rl) * ID + col) =
                        make_float2(v0, v1);
                }
            }
        }
}

// ---------------- GEMM2: out (+)= act @ Wd -----------------------------------
// Tile M=128 x N=128, K-chunk 16, double-buffered; B [k][n] + ldsm.trans.
template <bool ROUTED>
__global__ void __launch_bounds__(256) gemm2_mma(const float* __restrict__ Wd_all,
                                                 float* __restrict__ out) {
    const int e       = ROUTED ? blockIdx.z : 0;
    const int rows    = ROUTED ? g_counts[e] : TOK;
    const int row_off = ROUTED ? g_offsets[e] : 0;
    const int mtile   = blockIdx.y;
    if (mtile * 128 >= rows) return;
    const int ncol0 = blockIdx.x * 128;

    __shared__ __align__(16) __nv_bfloat16 sAh[2][128 * RS];
    __shared__ __align__(16) __nv_bfloat16 sAl[2][128 * RS];
    __shared__ __align__(16) __nv_bfloat16 sWh[2][16 * RSB2];
    __shared__ __align__(16) __nv_bfloat16 sWl[2][16 * RSB2];

    const int tid = threadIdx.x, wid = tid >> 5, lane = tid & 31;
    const int wm = wid >> 1, wn = wid & 1;

    const int a_off = (wm * 32 + (lane & 7) + ((lane >> 3) & 1) * 8) * RS + (lane >> 4) * 8;
    const int b_off = (lane & 15) * RSB2 + (lane >> 4) * 8;

    const int ar  = tid >> 1;
    const int acq = (tid & 1) * 8;
    const int abase = (ROUTED ? row_off : 0) + mtile * 128;
    const float* Arow = g_act + (size_t)(abase + ar) * ID;

    const int bk  = tid >> 4;
    const int bn8 = (tid & 15) * 8;
    const float* Wd = Wd_all + (ROUTED ? (size_t)e * ID * HD : 0);

    float4 va0, va1, vw0, vw1;
#define G2_LOAD(kb)                                                            \
    do {                                                                       \
        va0 = *(const float4*)(Arow + (kb) + acq);                             \
        va1 = *(const float4*)(Arow + (kb) + acq + 4);                         \
        const float* wdp = Wd + (size_t)((kb) + bk) * HD + ncol0 + bn8;        \
        vw0 = *(const float4*)(wdp);                                           \
        vw1 = *(const float4*)(wdp + 4);                                       \
    } while (0)

#define G2_STORE(s)                                                            \
    do {                                                                       \
        uint4 ph, pl;                                                          \
        ph.x = hi2(va0.x, va0.y); ph.y = hi2(va0.z, va0.w);                    \
        ph.z = hi2(va1.x, va1.y); ph.w = hi2(va1.z, va1.w);                    \
        pl.x = lo2(va0.x, va0.y); pl.y = lo2(va0.z, va0.w);                    \
        pl.z = lo2(va1.x, va1.y); pl.w = lo2(va1.z, va1.w);                    \
        *(uint4*)&sAh[s][ar * RS + acq] = ph;                                  \
        *(uint4*)&sAl[s][ar * RS + acq] = pl;                                  \
        uint4 wh, wl;                                                          \
        wh.x = hi2(vw0.x, vw0.y); wh.y = hi2(vw0.z, vw0.w);                    \
        wh.z = hi2(vw1.x, vw1.y); wh.w = hi2(vw1.z, vw1.w);                    \
        wl.x = lo2(vw0.x, vw0.y); wl.y = lo2(vw0.z, vw0.w);                    \
        wl.z = lo2(vw1.x, vw1.y); wl.w = lo2(vw1.z, vw1.w);                    \
        *(uint4*)&sWh[s][bk * RSB2 + bn8] = wh;                                \
        *(uint4*)&sWl[s][bk * RSB2 + bn8] = wl;                                \
    } while (0)

    float acc[2][8][4] = {};

    const int NCH = ID / 16;
    G2_LOAD(0);
    G2_STORE(0);
    G2_LOAD(16);
    __syncthreads();

    for (int ch = 0; ch < NCH; ch++) {
        const int cur = ch & 1, nxt = cur ^ 1;
        if (ch + 1 < NCH) G2_STORE(nxt);
        if (ch + 2 < NCH) G2_LOAD((ch + 2) * 16);

        uint32_t afh[2][4], afl[2][4];
#pragma unroll
        for (int am = 0; am < 2; am++) {
            ldsm4(afh[am], &sAh[cur][a_off + am * 16 * RS]);
            ldsm4(afl[am], &sAl[cur][a_off + am * 16 * RS]);
        }
        uint32_t bwh[4][4], bwl[4][4];
#pragma unroll
        for (int p = 0; p < 4; p++) {
            int nofs = wn * 64 + p * 16;
            ldsm4t(bwh[p], &sWh[cur][b_off + nofs]);
            ldsm4t(bwl[p], &sWl[cur][b_off + nofs]);
        }
#pragma unroll
        for (int an = 0; an < 8; an++) {
            const uint32_t* bh = &bwh[an >> 1][(an & 1) * 2];
            const uint32_t* bl = &bwl[an >> 1][(an & 1) * 2];
#pragma unroll
            for (int am = 0; am < 2; am++) {
                mma16816(acc[am][an], afh[am], bh);
                mma16816(acc[am][an], afh[am], bl);
                mma16816(acc[am][an], afl[am], bh);
            }
        }
        __syncthreads();
    }
#undef G2_LOAD
#undef G2_STORE

    // epilogue: write/accumulate fp32 output per token
#pragma unroll
    for (int am = 0; am < 2; am++)
#pragma unroll
        for (int an = 0; an < 8; an++) {
            int rl0 = wm * 32 + am * 16 + (lane >> 2);
            int col = ncol0 + wn * 64 + an * 8 + (lane & 3) * 2;
#pragma unroll
            for (int h = 0; h < 2; h++) {
                int rl = rl0 + h * 8;
                int r = mtile * 128 + rl;
                if (r < rows) {
                    int token = ROUTED ? g_sorted[row_off + r] : r;
                    float* po = out + (size_t)token * HD + col;
                    float v0 = acc[am][an][h * 2], v1 = acc[am][an][h * 2 + 1];
                    if (ROUTED) {
                        float2 o2 = *(float2*)po;
                        v0 += o2.x; v1 += o2.y;
                    }
                    *(float2*)po = make_float2(v0, v1);
                }
            }
        }
}

// ---------------- launch -----------------------------------------------------
extern "C" void kernel_launch(void* const* d_in, const int* in_sizes, int n_in,
                              void* d_out, int out_size) {
    (void)in_sizes; (void)n_in; (void)out_size;
    const float* x       = (const float*)d_in[0];
    const float* gate_w  = (const float*)d_in[1];
    const float* sh_gate = (const float*)d_in[2];
    const float* sh_up   = (const float*)d_in[3];
    const float* sh_down = (const float*)d_in[4];
    const float* rt_gate = (const float*)d_in[5];
    const float* rt_up   = (const float*)d_in[6];
    const float* rt_down = (const float*)d_in[7];
    float* out = (float*)d_out;

    // routing
    init_kernel<<<1, 32>>>();
    router_kernel<<<TOK / 8, 256>>>(x, gate_w);
    scan_kernel<<<1, 32>>>();
    build_sorted_kernel<<<TOK / 256, 256>>>();

    // shared expert first (act buffer reuse; writes full out, covers poison)
    gemm1_mma<false><<<dim3(ID / 64, TOK / 128, 1), 256>>>(x, sh_gate, sh_up);
    gemm2_mma<false><<<dim3(HD / 128, TOK / 128, 1), 256>>>(sh_down, out);

    // routed experts (scatter-add into out)
    gemm1_mma<true><<<dim3(ID / 64, TOK / 128, NE), 256>>>(x, rt_gate, rt_up);
    gemm2_mma<true><<<dim3(HD / 128, TOK / 128, NE), 256>>>(rt_down, out);
}

// round 10
// speedup vs baseline: 3.7017x; 1.1063x over previous
#include <cuda_runtime.h>
#include <cuda_bf16.h>
#include <math.h>
#include <stdint.h>

#define TOK 2048
#define HD  1024
#define ID  2048
#define NE  8
#define PAD 128
#define RS   24   // A smem row stride (elems): conflict-free ldsm + frags
#define RSB1 72   // gemm1 B smem row stride [k][n] (64 n + 8 pad)
#define RSB2 136  // gemm2 B smem row stride [k][n] (128 n + 8 pad)

// ---------------- scratch (device globals; ~41MB total — proven-safe scale) --
__device__ __align__(256) float g_xs[(size_t)TOK * HD];              // scored tokens fp32
__device__ __align__(256) __nv_bfloat16 g_xh[(size_t)TOK * HD];      // x hi (natural)
__device__ __align__(256) __nv_bfloat16 g_xl[(size_t)TOK * HD];      // x lo (natural)
__device__ __align__(256) __nv_bfloat16 g_xsh[(size_t)(TOK + PAD) * HD]; // xs hi (sorted)
__device__ __align__(256) __nv_bfloat16 g_xsl[(size_t)(TOK + PAD) * HD]; // xs lo (sorted)
__device__ __align__(256) __nv_bfloat16 g_ah[(size_t)(TOK + PAD) * ID];  // act hi
__device__ __align__(256) __nv_bfloat16 g_al[(size_t)(TOK + PAD) * ID];  // act lo
__device__ int g_expert[TOK];
__device__ int g_counts[NE];
__device__ int g_offsets[NE];
__device__ int g_cursor[NE];
__device__ int g_sorted[TOK];

// ---------------- helpers ----------------------------------------------------
__device__ __forceinline__ void mma16816(float* d, const uint32_t* a, const uint32_t* b) {
    asm volatile(
        "mma.sync.aligned.m16n8k16.row.col.f32.bf16.bf16.f32 "
        "{%0,%1,%2,%3}, {%4,%5,%6,%7}, {%8,%9}, {%0,%1,%2,%3};"
        : "+f"(d[0]), "+f"(d[1]), "+f"(d[2]), "+f"(d[3])
        : "r"(a[0]), "r"(a[1]), "r"(a[2]), "r"(a[3]), "r"(b[0]), "r"(b[1]));
}
__device__ __forceinline__ void ldsm4(uint32_t* r, const void* p) {
    uint32_t a = (uint32_t)__cvta_generic_to_shared(p);
    asm volatile("ldmatrix.sync.aligned.m8n8.x4.shared.b16 {%0,%1,%2,%3}, [%4];"
                 : "=r"(r[0]), "=r"(r[1]), "=r"(r[2]), "=r"(r[3]) : "r"(a));
}
__device__ __forceinline__ void ldsm4t(uint32_t* r, const void* p) {
    uint32_t a = (uint32_t)__cvta_generic_to_shared(p);
    asm volatile("ldmatrix.sync.aligned.m8n8.x4.trans.shared.b16 {%0,%1,%2,%3}, [%4];"
                 : "=r"(r[0]), "=r"(r[1]), "=r"(r[2]), "=r"(r[3]) : "r"(a));
}
// hi split by truncation: upper 16 bits of fp32 == bf16 (round-toward-zero)
__device__ __forceinline__ uint32_t hi2(float a, float b) {
    return __byte_perm(__float_as_uint(a), __float_as_uint(b), 0x7632);
}
__device__ __forceinline__ float hif(float a) {
    return __uint_as_float(__float_as_uint(a) & 0xFFFF0000u);
}
__device__ __forceinline__ uint32_t lo2(float a, float b) {
    __nv_bfloat162 t = __floats2bfloat162_rn(a - hif(a), b - hif(b));
    return reinterpret_cast<uint32_t&>(t);
}

// ---------------- small kernels ---------------------------------------------
__global__ void init_kernel() {
    if (threadIdx.x < NE) g_counts[threadIdx.x] = 0;
}

__global__ void router_kernel(const float* __restrict__ x,
                              const float* __restrict__ gate_w) {
    int warp = (blockIdx.x * blockDim.x + threadIdx.x) >> 5;
    int lane = threadIdx.x & 31;
    if (warp >= TOK) return;
    const float* xr = x + (size_t)warp * HD;
    float acc[NE];
#pragma unroll
    for (int e = 0; e < NE; e++) acc[e] = 0.f;
    for (int h = lane; h < HD; h += 32) {
        float xv = xr[h];
        const float* w = gate_w + (size_t)h * NE;
#pragma unroll
        for (int e = 0; e < NE; e++) acc[e] = fmaf(xv, w[e], acc[e]);
    }
#pragma unroll
    for (int e = 0; e < NE; e++) {
#pragma unroll
        for (int o = 16; o > 0; o >>= 1)
            acc[e] += __shfl_xor_sync(0xffffffffu, acc[e], o);
    }
    int best = 0; float bv = acc[0];
#pragma unroll
    for (int e = 1; e < NE; e++) if (acc[e] > bv) { bv = acc[e]; best = e; }
    float score = 1.f / (1.f + expf(-bv));
    if (lane == 0) {
        g_expert[warp] = best;
        atomicAdd(&g_counts[best], 1);
    }
    float* dst = g_xs + (size_t)warp * HD;
    for (int h = lane; h < HD; h += 32) dst[h] = xr[h] * score;
}

__global__ void scan_kernel() {
    if (threadIdx.x == 0) {
        int off = 0;
        for (int e = 0; e < NE; e++) {
            g_offsets[e] = off;
            g_cursor[e]  = off;
            off += g_counts[e];
        }
    }
}

__global__ void build_sorted_kernel() {
    int t = blockIdx.x * blockDim.x + threadIdx.x;
    if (t >= TOK) return;
    int e = g_expert[t];
    int pos = atomicAdd(&g_cursor[e], 1);
    g_sorted[pos] = t;
}

// split x (natural) and scored-x (sorted order) into bf16 hi/lo
__global__ void __launch_bounds__(256) pack_x_kernel(const float* __restrict__ x) {
    int t = blockIdx.x;
    int src = g_sorted[t];
    const float* xp = x + (size_t)t * HD;
    const float* sp = g_xs + (size_t)src * HD;
    for (int h = threadIdx.x * 2; h < HD; h += 512) {
        float2 a = *(const float2*)(xp + h);
        *(uint32_t*)(g_xh + (size_t)t * HD + h) = hi2(a.x, a.y);
        *(uint32_t*)(g_xl + (size_t)t * HD + h) = lo2(a.x, a.y);
        float2 b = *(const float2*)(sp + h);
        *(uint32_t*)(g_xsh + (size_t)t * HD + h) = hi2(b.x, b.y);
        *(uint32_t*)(g_xsl + (size_t)t * HD + h) = lo2(b.x, b.y);
    }
}

// ---------------- GEMM1: act = silu(A@Wg)*(A@Wu) -----------------------------
// Tile M=128 x N=64, K-chunk 16, double-buffered. A pre-split bf16 (no convert);
// B [k][n] + ldsm.trans with in-loop truncation split. 2 CTAs/SM.
template <bool ROUTED>
__global__ void __launch_bounds__(256, 2) gemm1_mma(const float* __restrict__ Wg_all,
                                                    const float* __restrict__ Wu_all) {
    const int e       = ROUTED ? blockIdx.z : 0;
    const int rows    = ROUTED ? g_counts[e] : TOK;
    const int row_off = ROUTED ? g_offsets[e] : 0;
    const int mtile   = blockIdx.y;
    if (mtile * 128 >= rows) return;
    const int ncol0 = blockIdx.x * 64;

    __shared__ __align__(16) __nv_bfloat16 sAh[2][128 * RS];
    __shared__ __align__(16) __nv_bfloat16 sAl[2][128 * RS];
    __shared__ __align__(16) __nv_bfloat16 sGh[2][16 * RSB1];
    __shared__ __align__(16) __nv_bfloat16 sGl[2][16 * RSB1];
    __shared__ __align__(16) __nv_bfloat16 sUh[2][16 * RSB1];
    __shared__ __align__(16) __nv_bfloat16 sUl[2][16 * RSB1];

    const int tid = threadIdx.x, wid = tid >> 5, lane = tid & 31;
    const int wm = wid >> 1, wn = wid & 1;

    // ldmatrix lane offsets
    const int a_off = (wm * 32 + (lane & 7) + ((lane >> 3) & 1) * 8) * RS + (lane >> 4) * 8;
    const int b_off = (lane & 15) * RSB1 + (lane >> 4) * 8;   // trans: k row, n col

    // A loader: row ar (0..127), 8 bf16 cols (16B) at acq
    const int ar  = tid >> 1;
    const int acq = (tid & 1) * 8;
    size_t arow_idx = (size_t)((ROUTED ? row_off : 0) + mtile * 128 + ar);
    const __nv_bfloat16* Ah = (ROUTED ? g_xsh : g_xh) + arow_idx * HD;
    const __nv_bfloat16* Al = (ROUTED ? g_xsl : g_xl) + arow_idx * HD;
    // B loader: k = bk (0..15), 4 n at bn4
    const int bk  = tid >> 4;
    const int bn4 = (tid & 15) * 4;
    const float* Wg = Wg_all + (ROUTED ? (size_t)e * HD * ID : 0);
    const float* Wu = Wu_all + (ROUTED ? (size_t)e * HD * ID : 0);

    uint4 vah, val;
    float4 vg, vu;
#define G1_LOAD(kb)                                                            \
    do {                                                                       \
        vah = *(const uint4*)(Ah + (kb) + acq);                                \
        val = *(const uint4*)(Al + (kb) + acq);                                \
        vg  = *(const float4*)(Wg + (size_t)((kb) + bk) * ID + ncol0 + bn4);   \
        vu  = *(const float4*)(Wu + (size_t)((kb) + bk) * ID + ncol0 + bn4);   \
    } while (0)

#define G1_STORE(s)                                                            \
    do {                                                                       \
        *(uint4*)&sAh[s][ar * RS + acq] = vah;                                 \
        *(uint4*)&sAl[s][ar * RS + acq] = val;                                 \
        *(uint2*)&sGh[s][bk * RSB1 + bn4] =                                    \
            make_uint2(hi2(vg.x, vg.y), hi2(vg.z, vg.w));                      \
        *(uint2*)&sGl[s][bk * RSB1 + bn4] =                                    \
            make_uint2(lo2(vg.x, vg.y), lo2(vg.z, vg.w));                      \
        *(uint2*)&sUh[s][bk * RSB1 + bn4] =                                    \
            make_uint2(hi2(vu.x, vu.y), hi2(vu.z, vu.w));                      \
        *(uint2*)&sUl[s][bk * RSB1 + bn4] =                                    \
            make_uint2(lo2(vu.x, vu.y), lo2(vu.z, vu.w));                      \
    } while (0)

    float accg[2][4][4] = {};
    float accu[2][4][4] = {};

    const int NCH = HD / 16;
    G1_LOAD(0);
    G1_STORE(0);
    G1_LOAD(16);
    __syncthreads();

    for (int ch = 0; ch < NCH; ch++) {
        const int cur = ch & 1, nxt = cur ^ 1;
        if (ch + 1 < NCH) G1_STORE(nxt);              // regs hold chunk ch+1
        if (ch + 2 < NCH) G1_LOAD((ch + 2) * 16);     // overlaps MMAs

        uint32_t afh[2][4], afl[2][4];
#pragma unroll
        for (int am = 0; am < 2; am++) {
            ldsm4(afh[am], &sAh[cur][a_off + am * 16 * RS]);
            ldsm4(afl[am], &sAl[cur][a_off + am * 16 * RS]);
        }
#pragma unroll
        for (int p = 0; p < 2; p++) {
            uint32_t bgh[4], bgl[4], buh[4], bul[4];
            int nofs = wn * 32 + p * 16;
            ldsm4t(bgh, &sGh[cur][b_off + nofs]);
            ldsm4t(bgl, &sGl[cur][b_off + nofs]);
            ldsm4t(buh, &sUh[cur][b_off + nofs]);
            ldsm4t(bul, &sUl[cur][b_off + nofs]);
#pragma unroll
            for (int q = 0; q < 2; q++) {
                int an = p * 2 + q;
                const uint32_t* bh = &bgh[q * 2];
                const uint32_t* bl = &bgl[q * 2];
                const uint32_t* uh = &buh[q * 2];
                const uint32_t* ul = &bul[q * 2];
#pragma unroll
                for (int am = 0; am < 2; am++) {
                    mma16816(accg[am][an], afh[am], bh);
                    mma16816(accg[am][an], afh[am], bl);
                    mma16816(accg[am][an], afl[am], bh);
                    mma16816(accu[am][an], afh[am], uh);
                    mma16816(accu[am][an], afh[am], ul);
                    mma16816(accu[am][an], afl[am], uh);
                }
            }
        }
        __syncthreads();
    }
#undef G1_LOAD
#undef G1_STORE

    // epilogue: silu(g)*u -> bf16 hi/lo act (sorted order for routed)
    const int obase = (ROUTED ? row_off : 0) + mtile * 128;
#pragma unroll
    for (int am = 0; am < 2; am++)
#pragma unroll
        for (int an = 0; an < 4; an++) {
            int rl0 = wm * 32 + am * 16 + (lane >> 2);
            int col = ncol0 + wn * 32 + an * 8 + (lane & 3) * 2;
#pragma unroll
            for (int h = 0; h < 2; h++) {
                int rl = rl0 + h * 8;
                if (mtile * 128 + rl < rows) {
                    float g0 = accg[am][an][h * 2], g1 = accg[am][an][h * 2 + 1];
                    float u0 = accu[am][an][h * 2], u1 = accu[am][an][h * 2 + 1];
                    float v0 = g0 / (1.f + __expf(-g0)) * u0;
                    float v1 = g1 / (1.f + __expf(-g1)) * u1;
                    size_t o = (size_t)(obase + rl) * ID + col;
                    *(uint32_t*)(g_ah + o) = hi2(v0, v1);
                    *(uint32_t*)(g_al + o) = lo2(v0, v1);
                }
            }
        }
}

// ---------------- GEMM2: out (+)= act @ Wd -----------------------------------
// Tile M=128 x N=128, K-chunk 16, double-buffered; A pre-split bf16; 2 CTAs/SM.
template <bool ROUTED>
__global__ void __launch_bounds__(256, 2) gemm2_mma(const float* __restrict__ Wd_all,
                                                    float* __restrict__ out) {
    const int e       = ROUTED ? blockIdx.z : 0;
    const int rows    = ROUTED ? g_counts[e] : TOK;
    const int row_off = ROUTED ? g_offsets[e] : 0;
    const int mtile   = blockIdx.y;
    if (mtile * 128 >= rows) return;
    const int ncol0 = blockIdx.x * 128;

    __shared__ __align__(16) __nv_bfloat16 sAh[2][128 * RS];
    __shared__ __align__(16) __nv_bfloat16 sAl[2][128 * RS];
    __shared__ __align__(16) __nv_bfloat16 sWh[2][16 * RSB2];
    __shared__ __align__(16) __nv_bfloat16 sWl[2][16 * RSB2];

    const int tid = threadIdx.x, wid = tid >> 5, lane = tid & 31;
    const int wm = wid >> 1, wn = wid & 1;

    const int a_off = (wm * 32 + (lane & 7) + ((lane >> 3) & 1) * 8) * RS + (lane >> 4) * 8;
    const int b_off = (lane & 15) * RSB2 + (lane >> 4) * 8;

    const int ar  = tid >> 1;
    const int acq = (tid & 1) * 8;
    const size_t arow_idx = (size_t)((ROUTED ? row_off : 0) + mtile * 128 + ar);
    const __nv_bfloat16* Ah = g_ah + arow_idx * ID;
    const __nv_bfloat16* Al = g_al + arow_idx * ID;

    const int bk  = tid >> 4;
    const int bn8 = (tid & 15) * 8;
    const float* Wd = Wd_all + (ROUTED ? (size_t)e * ID * HD : 0);

    uint4 vah, val;
    float4 vw0, vw1;
#define G2_LOAD(kb)                                                            \
    do {                                                                       \
        vah = *(const uint4*)(Ah + (kb) + acq);                                \
        val = *(const uint4*)(Al + (kb) + acq);                                \
        const float* wdp = Wd + (size_t)((kb) + bk) * HD + ncol0 + bn8;        \
        vw0 = *(const float4*)(wdp);                                           \
        vw1 = *(const float4*)(wdp + 4);                                       \
    } while (0)

#define G2_STORE(s)                                                            \
    do {                                                                       \
        *(uint4*)&sAh[s][ar * RS + acq] = vah;                                 \
        *(uint4*)&sAl[s][ar * RS + acq] = val;                                 \
        uint4 wh, wl;                                                          \
        wh.x = hi2(vw0.x, vw0.y); wh.y = hi2(vw0.z, vw0.w);                    \
        wh.z = hi2(vw1.x, vw1.y); wh.w = hi2(vw1.z, vw1.w);                    \
        wl.x = lo2(vw0.x, vw0.y); wl.y = lo2(vw0.z, vw0.w);                    \
        wl.z = lo2(vw1.x, vw1.y); wl.w = lo2(vw1.z, vw1.w);                    \
        *(uint4*)&sWh[s][bk * RSB2 + bn8] = wh;                                \
        *(uint4*)&sWl[s][bk * RSB2 + bn8] = wl;                                \
    } while (0)

    float acc[2][8][4] = {};

    const int NCH = ID / 16;
    G2_LOAD(0);
    G2_STORE(0);
    G2_LOAD(16);
    __syncthreads();

    for (int ch = 0; ch < NCH; ch++) {
        const int cur = ch & 1, nxt = cur ^ 1;
        if (ch + 1 < NCH) G2_STORE(nxt);
        if (ch + 2 < NCH) G2_LOAD((ch + 2) * 16);

        uint32_t afh[2][4], afl[2][4];
#pragma unroll
        for (int am = 0; am < 2; am++) {
            ldsm4(afh[am], &sAh[cur][a_off + am * 16 * RS]);
            ldsm4(afl[am], &sAl[cur][a_off + am * 16 * RS]);
        }
#pragma unroll
        for (int p = 0; p < 4; p++) {
            uint32_t bwh[4], bwl[4];
            int nofs = wn * 64 + p * 16;
            ldsm4t(bwh, &sWh[cur][b_off + nofs]);
            ldsm4t(bwl, &sWl[cur][b_off + nofs]);
#pragma unroll
            for (int q = 0; q < 2; q++) {
                int an = p * 2 + q;
                const uint32_t* bh = &bwh[q * 2];
                const uint32_t* bl = &bwl[q * 2];
#pragma unroll
                for (int am = 0; am < 2; am++) {
                    mma16816(acc[am][an], afh[am], bh);
                    mma16816(acc[am][an], afh[am], bl);
                    mma16816(acc[am][an], afl[am], bh);
                }
            }
        }
        __syncthreads();
    }
#undef G2_LOAD
#undef G2_STORE

    // epilogue: write/accumulate fp32 output per token
#pragma unroll
    for (int am = 0; am < 2; am++)
#pragma unroll
        for (int an = 0; an < 8; an++) {
            int rl0 = wm * 32 + am * 16 + (lane >> 2);
            int col = ncol0 + wn * 64 + an * 8 + (lane & 3) * 2;
#pragma unroll
            for (int h = 0; h < 2; h++) {
                int rl = rl0 + h * 8;
                int r = mtile * 128 + rl;
                if (r < rows) {
                    int token = ROUTED ? g_sorted[row_off + r] : r;
                    float* po = out + (size_t)token * HD + col;
                    float v0 = acc[am][an][h * 2], v1 = acc[am][an][h * 2 + 1];
                    if (ROUTED) {
                        float2 o2 = *(float2*)po;
                        v0 += o2.x; v1 += o2.y;
                    }
                    *(float2*)po = make_float2(v0, v1);
                }
            }
        }
}

// ---------------- launch -----------------------------------------------------
extern "C" void kernel_launch(void* const* d_in, const int* in_sizes, int n_in,
                              void* d_out, int out_size) {
    (void)in_sizes; (void)n_in; (void)out_size;
    const float* x       = (const float*)d_in[0];
    const float* gate_w  = (const float*)d_in[1];
    const float* sh_gate = (const float*)d_in[2];
    const float* sh_up   = (const float*)d_in[3];
    const float* sh_down = (const float*)d_in[4];
    const float* rt_gate = (const float*)d_in[5];
    const float* rt_up   = (const float*)d_in[6];
    const float* rt_down = (const float*)d_in[7];
    float* out = (float*)d_out;

    // routing + activation pre-split
    init_kernel<<<1, 32>>>();
    router_kernel<<<TOK / 8, 256>>>(x, gate_w);
    scan_kernel<<<1, 32>>>();
    build_sorted_kernel<<<TOK / 256, 256>>>();
    pack_x_kernel<<<TOK, 256>>>(x);

    // shared expert first (act buffer reuse; writes full out, covers poison)
    gemm1_mma<false><<<dim3(ID / 64, TOK / 128, 1), 256>>>(sh_gate, sh_up);
    gemm2_mma<false><<<dim3(HD / 128, TOK / 128, 1), 256>>>(sh_down, out);

    // routed experts (scatter-add into out)
    gemm1_mma<true><<<dim3(ID / 64, TOK / 128, NE), 256>>>(rt_gate, rt_up);
    gemm2_mma<true><<<dim3(HD / 128, TOK / 128, NE), 256>>>(rt_down, out);
}